// round 12
// baseline (speedup 1.0000x reference)
#include <cuda_runtime.h>
#include <cuda_bf16.h>
#include <cstdint>
#include <cstddef>

// ---- problem constants ----
#define Bb   2
#define Ss   1568
#define Dd   768
#define Hh   12
#define HDd  64
#define Ff   8
#define NSP  196
#define BS   (Bb*Ss)             // 3136
#define BSD  (Bb*Ss*Dd)          // 2408448
#define XSZ  (Bb*Ss*Ff*Dd)       // 19267584
#define SCALE 0.125f

// ---- scratch ----
__device__ float g_m[(size_t)BS*Hh*Dd];      // [t][h][768] fp32 logit-matrices
__device__ float g_zerob[768];               // zero bias (static-zeroed)
__device__ float g_bqkv[3*768];              // packed bq|bk|bv

// bf16 hi/lo planes (contiguous for batched GEMMs)
__device__ __align__(16) __nv_bfloat16 g_inh[3*BSD], g_inl[3*BSD];     // query|key|value split
__device__ __align__(16) __nv_bfloat16 g_qkvh[3*BSD], g_qkvl[3*BSD];   // projected q|k|v
__device__ __align__(16) __nv_bfloat16 g_xh [XSZ], g_xl [XSZ];
__device__ __align__(16) __nv_bfloat16 g_xdh[BSD], g_xdl[BSD];
__device__ __align__(16) __nv_bfloat16 g_q2h[BSD], g_q2l[BSD];
__device__ __align__(16) __nv_bfloat16 g_xwh[(size_t)BS*Hh*Dd], g_xwl[(size_t)BS*Hh*Dd];
__device__ __align__(16) __nv_bfloat16 g_t2h[BSD], g_t2l[BSD];
__device__ __align__(16) __nv_bfloat16 g_wk2h[768*768], g_wk2l[768*768]; // Wpkv[:, :768] row-major split

// transposed+split weights: [N][K] bf16, hi and lo parts
#define WSQ  (768*768)
#define OFF_WQ   0
#define OFF_WK   (1*WSQ)
#define OFF_WV   (2*WSQ)
#define OFF_WPQ  (3*WSQ)
#define OFF_WP   (4*WSQ)
#define OFF_WPKV (5*WSQ)
#define WT_ELEMS (5*WSQ + 1536*768)
__device__ __align__(16) __nv_bfloat16 g_wth[WT_ELEMS];
__device__ __align__(16) __nv_bfloat16 g_wtl[WT_ELEMS];

// ============================================================
// helpers
// ============================================================
__device__ __forceinline__ uint32_t smem_u32(const void* p) {
    uint32_t a;
    asm("{ .reg .u64 t; cvta.to.shared.u64 t, %1; cvt.u32.u64 %0, t; }" : "=r"(a) : "l"(p));
    return a;
}
__device__ __forceinline__ void ldmx4(uint32_t* r, uint32_t a) {
    asm volatile("ldmatrix.sync.aligned.m8n8.x4.shared.b16 {%0,%1,%2,%3}, [%4];"
        : "=r"(r[0]), "=r"(r[1]), "=r"(r[2]), "=r"(r[3]) : "r"(a));
}
__device__ __forceinline__ void ldmx4t(uint32_t* r, uint32_t a) {
    asm volatile("ldmatrix.sync.aligned.m8n8.x4.trans.shared.b16 {%0,%1,%2,%3}, [%4];"
        : "=r"(r[0]), "=r"(r[1]), "=r"(r[2]), "=r"(r[3]) : "r"(a));
}
__device__ __forceinline__ void mma_bf16(float* c, const uint32_t* a, const uint32_t* b) {
    asm volatile("mma.sync.aligned.m16n8k16.row.col.f32.bf16.bf16.f32 "
        "{%0,%1,%2,%3}, {%4,%5,%6,%7}, {%8,%9}, {%0,%1,%2,%3};"
        : "+f"(c[0]), "+f"(c[1]), "+f"(c[2]), "+f"(c[3])
        : "r"(a[0]), "r"(a[1]), "r"(a[2]), "r"(a[3]), "r"(b[0]), "r"(b[1]));
}
#define CP_ASYNC16(dst, src, sz) \
    asm volatile("cp.async.cg.shared.global [%0], [%1], 16, %2;" \
                 :: "r"(dst), "l"(src), "r"(sz))
#define CP_COMMIT() asm volatile("cp.async.commit_group;" ::: "memory")
#define CP_WAIT(n)  asm volatile("cp.async.wait_group %0;" :: "n"(n) : "memory")

__device__ __forceinline__ void split2(float a, float b, uint32_t& h, uint32_t& l) {
    __nv_bfloat162 hh = __floats2bfloat162_rn(a, b);
    float2 f = __bfloat1622float2(hh);
    __nv_bfloat162 ll = __floats2bfloat162_rn(a - f.x, b - f.y);
    h = *(uint32_t*)&hh; l = *(uint32_t*)&ll;
}

// ============================================================
// Weight transpose + bf16 split: W[K][N] fp32 -> hi/lo [N][K] bf16
// ============================================================
__global__ void wtrans_kernel(const float* __restrict__ W,
                              __nv_bfloat16* __restrict__ hi,
                              __nv_bfloat16* __restrict__ lo, int K, int N)
{
    __shared__ float t[32][33];
    int n0 = blockIdx.x * 32, k0 = blockIdx.y * 32;
    int tx = threadIdx.x, ty = threadIdx.y;
#pragma unroll
    for (int i = 0; i < 32; i += 8)
        t[ty + i][tx] = W[(size_t)(k0 + ty + i) * N + n0 + tx];
    __syncthreads();
#pragma unroll
    for (int i = 0; i < 32; i += 8) {
        float v = t[tx][ty + i];
        __nv_bfloat16 h = __float2bfloat16(v);
        __nv_bfloat16 l = __float2bfloat16(v - __bfloat162float(h));
        size_t o = (size_t)(n0 + ty + i) * K + k0 + tx;
        hi[o] = h; lo[o] = l;
    }
}

// ============================================================
// merged elementwise fp32 -> bf16 hi/lo planes (3 inputs via grid.y)
// ============================================================
__global__ void split3_kernel(const float4* __restrict__ a0, const float4* __restrict__ a1,
                              const float4* __restrict__ a2,
                              uint2* __restrict__ H, uint2* __restrict__ L, int n4)
{
    int i = blockIdx.x * blockDim.x + threadIdx.x;
    if (i >= n4) return;
    int which = blockIdx.y;
    const float4* in = which == 0 ? a0 : (which == 1 ? a1 : a2);
    float4 a = in[i];
    uint32_t h01, l01, h23, l23;
    split2(a.x, a.y, h01, l01);
    split2(a.z, a.w, h23, l23);
    size_t o = (size_t)which * n4 + i;
    H[o] = make_uint2(h01, h23);
    L[o] = make_uint2(l01, l23);
}

// pack bq|bk|bv into one contiguous bias array
__global__ void biaspack_kernel(const float* __restrict__ b0, const float* __restrict__ b1,
                                const float* __restrict__ b2, float* __restrict__ dst)
{
    int i = blockIdx.x * blockDim.x + threadIdx.x;
    if (i >= 3*768) return;
    int w = i / 768, j = i % 768;
    dst[i] = (w == 0 ? b0 : (w == 1 ? b1 : b2))[j];
}

// split Wpkv[:, :768] row-major (no transpose): wk2[j][c] = Wpkv[j][c]
__global__ void splitwk2_kernel(const float* __restrict__ Wpkv,
                                __nv_bfloat16* __restrict__ H, __nv_bfloat16* __restrict__ L)
{
    int i = blockIdx.x * blockDim.x + threadIdx.x;   // over 768*192 float4s
    if (i >= 768*192) return;
    int j = i / 192, c4 = (i % 192) * 4;
    float4 a = *(const float4*)&Wpkv[(size_t)j * 1536 + c4];
    uint32_t h01, l01, h23, l23;
    split2(a.x, a.y, h01, l01);
    split2(a.z, a.w, h23, l23);
    *(uint2*)&H[(size_t)j*768 + c4] = make_uint2(h01, h23);
    *(uint2*)&L[(size_t)j*768 + c4] = make_uint2(l01, l23);
}

// ============================================================
// HMMA bf16x3 GEMM, templated: NTILE in {128, 64}, OUT_SPLIT in {0,1}
// ============================================================
template <int OUT_SPLIT, int NTILE>
__device__ __forceinline__ void gemm_body(
    const __nv_bfloat16* __restrict__ Ah, const __nv_bfloat16* __restrict__ Al, int lda,
    const __nv_bfloat16* __restrict__ Bh, const __nv_bfloat16* __restrict__ Bl, int ldb,
    const float* __restrict__ bias,
    float* __restrict__ C, __nv_bfloat16* __restrict__ CH, __nv_bfloat16* __restrict__ CL,
    int ldc, int M, int K)
{
    constexpr int NJ  = NTILE / 16;
    constexpr int BST = NTILE * 80;
    constexpr int STG = 20480 + 2 * BST;
    constexpr int CPN = 1024 + NTILE * 8;

    extern __shared__ char smem[];
    const uint32_t sb = smem_u32(smem);
    const int tid = threadIdx.x;
    const int wid = tid >> 5, lane = tid & 31;
    const int bm = blockIdx.y * 128, bn = blockIdx.x * NTILE;
    const int m0 = (wid & 3) * 32;
    const int n0 = (wid >> 2) * (NTILE / 2);

    float c[2][NJ][4];
#pragma unroll
    for (int i = 0; i < 2; i++)
#pragma unroll
        for (int j = 0; j < NJ; j++)
#pragma unroll
            for (int e = 0; e < 4; e++) c[i][j][e] = 0.f;

    const int ra = (lane & 7) + ((lane >> 3) & 1) * 8;
    const int ca = (lane >> 4) & 1;
    const int rb = (lane & 7) + ((lane >> 4) & 1) * 8;
    const int cb = (lane >> 3) & 1;

    auto issue = [&](int kb, int s) {
        for (int i = tid; i < CPN; i += 256) {
            uint32_t dst, sz = 16;
            const __nv_bfloat16* src;
            if (i < 1024) {
                int p = i >> 9, rem = i & 511;
                int row = rem >> 2, c4 = rem & 3;
                dst = sb + s * STG + p * 10240 + row * 80 + c4 * 16;
                int gm = bm + row;
                int g  = gm < M ? gm : 0;
                if (gm >= M) sz = 0;
                src = (p == 0 ? Ah : Al) + (size_t)g * lda + kb + c4 * 8;
            } else {
                int i2 = i - 1024;
                int p = i2 / (NTILE * 4), rem = i2 % (NTILE * 4);
                int row = rem >> 2, c4 = rem & 3;
                dst = sb + s * STG + 20480 + p * BST + row * 80 + c4 * 16;
                src = (p == 0 ? Bh : Bl) + (size_t)(bn + row) * ldb + kb + c4 * 8;
            }
            CP_ASYNC16(dst, src, sz);
        }
    };

    issue(0, 0);
    CP_COMMIT();

    int s = 0;
    for (int kb = 0; kb < K; kb += 32, s ^= 1) {
        if (kb + 32 < K) {
            issue(kb + 32, s ^ 1);
            CP_COMMIT();
            CP_WAIT(1);
        } else {
            CP_WAIT(0);
        }
        __syncthreads();

        uint32_t base = sb + s * STG;
        uint32_t aAh = base +     0 + (m0 + ra) * 80 + ca * 16;
        uint32_t aAl = base + 10240 + (m0 + ra) * 80 + ca * 16;
        uint32_t aBh = base + 20480 +       (n0 + rb) * 80 + cb * 16;
        uint32_t aBl = base + 20480 + BST + (n0 + rb) * 80 + cb * 16;

#pragma unroll
        for (int ks = 0; ks < 2; ks++) {
            uint32_t ah[2][4], al[2][4], bh[NJ/2][4], bl[NJ/2][4];
            ldmx4(ah[0], aAh + ks * 32);
            ldmx4(ah[1], aAh + 16 * 80 + ks * 32);
            ldmx4(al[0], aAl + ks * 32);
            ldmx4(al[1], aAl + 16 * 80 + ks * 32);
#pragma unroll
            for (int j = 0; j < NJ/2; j++) {
                ldmx4(bh[j], aBh + j * 16 * 80 + ks * 32);
                ldmx4(bl[j], aBl + j * 16 * 80 + ks * 32);
            }
#pragma unroll
            for (int mi = 0; mi < 2; mi++)
#pragma unroll
                for (int nj = 0; nj < NJ; nj++) {
                    const uint32_t* bhp = &bh[nj >> 1][(nj & 1) * 2];
                    const uint32_t* blp = &bl[nj >> 1][(nj & 1) * 2];
                    mma_bf16(c[mi][nj], ah[mi], bhp);
                    mma_bf16(c[mi][nj], al[mi], bhp);
                    mma_bf16(c[mi][nj], ah[mi], blp);
                }
        }
        __syncthreads();
    }

    const int cr = lane >> 2, cc = (lane & 3) * 2;
#pragma unroll
    for (int nj = 0; nj < NJ; nj++) {
        int bcol = bn + n0 + nj * 8 + cc;
        float b0 = bias[bcol], b1 = bias[bcol + 1];
#pragma unroll
        for (int mi = 0; mi < 2; mi++) {
#pragma unroll
            for (int hf = 0; hf < 2; hf++) {
                int r = bm + m0 + mi * 16 + cr + hf * 8;
                if (r >= M) continue;
                float o0 = c[mi][nj][hf*2+0] + b0;
                float o1 = c[mi][nj][hf*2+1] + b1;
                if (OUT_SPLIT) {
                    uint32_t h, l;
                    split2(o0, o1, h, l);
                    *(uint32_t*)&CH[(size_t)r * ldc + bcol] = h;
                    *(uint32_t*)&CL[(size_t)r * ldc + bcol] = l;
                } else {
                    *(float2*)&C[(size_t)r * ldc + bcol] = make_float2(o0, o1);
                }
            }
        }
    }
}

template <int OUT_SPLIT, int NTILE>
__global__ __launch_bounds__(256) void gemm_tpl(
    const __nv_bfloat16* Ah, const __nv_bfloat16* Al, int lda, long aZ,
    const __nv_bfloat16* Bh, const __nv_bfloat16* Bl, int ldb, long bZ,
    const float* bias, long biasZ,
    float* C, __nv_bfloat16* CH, __nv_bfloat16* CL, int ldc, long cZ,
    int M, int K)
{
    long z = blockIdx.z;
    gemm_body<OUT_SPLIT, NTILE>(
        Ah + z*aZ, Al + z*aZ, lda,
        Bh + z*bZ, Bl + z*bZ, ldb,
        bias + z*biasZ,
        C  ? C  + z*cZ : nullptr,
        CH ? CH + z*cZ : nullptr,
        CL ? CL + z*cZ : nullptr,
        ldc, M, K);
}

#define SMEM_128 81920
#define SMEM_64  61440

// ============================================================
// Stage 1 (HMMA): per (b,h,f, 128-query tile) fused attention.
// ============================================================
#define S1_OPH   0
#define S1_OPL   59392
#define S1_OQH   0
#define S1_OQL   18432
#define S1_OKH   36864
#define S1_OKL   69120
#define S1_OVH   118784
#define S1_OVL   151040
#define S1_ORMAX 183296
#define S1_ORSUM 184320
#define S1_SMEM  185344

__global__ __launch_bounds__(256) void stage1_mma_kernel(
    const __nv_bfloat16* __restrict__ Qh_, const __nv_bfloat16* __restrict__ Ql_,
    const __nv_bfloat16* __restrict__ Kh_, const __nv_bfloat16* __restrict__ Kl_,
    const __nv_bfloat16* __restrict__ Vh_, const __nv_bfloat16* __restrict__ Vl_,
    __nv_bfloat16* __restrict__ XH, __nv_bfloat16* __restrict__ XL,
    float* __restrict__ SA)
{
    extern __shared__ char sm[];
    const uint32_t sb = smem_u32(sm);
    const int tid = threadIdx.x;
    const int wid = tid >> 5, lane = tid & 31;
    const int wm = wid & 3, wn = wid >> 2;
    const int q0g = blockIdx.x * 128;
    const int f   = blockIdx.y;
    const int bh  = blockIdx.z;
    const int b   = bh / Hh, h = bh % Hh;

    for (int t = tid; t < 2048; t += 256) {
        int p = t >> 10, r = (t >> 3) & 127, ch = t & 7;
        int qg = q0g + r;
        uint4 v = make_uint4(0,0,0,0);
        if (qg < Ss) {
            const __nv_bfloat16* src = (p ? Ql_ : Qh_) + (size_t)(b*Ss + qg)*Dd + h*64 + ch*8;
            v = *(const uint4*)src;
        }
        *(uint4*)(sm + (p ? S1_OQL : S1_OQH) + r*144 + ch*16) = v;
    }
    for (int t = tid; t < 3584; t += 256) {
        int p = t / 1792, rem = t % 1792;
        int kk = rem >> 3, ch = rem & 7;
        uint4 v = make_uint4(0,0,0,0);
        if (kk < NSP) {
            const __nv_bfloat16* src = (p ? Kl_ : Kh_) + (size_t)(b*Ss + f*NSP + kk)*Dd + h*64 + ch*8;
            v = *(const uint4*)src;
        }
        *(uint4*)(sm + (p ? S1_OKL : S1_OKH) + kk*144 + ch*16) = v;
    }
    for (int t = tid; t < 3584; t += 256) {
        int p = t / 1792, rem = t % 1792;
        int kk = rem >> 3, ch = rem & 7;
        uint4 v = make_uint4(0,0,0,0);
        if (kk < NSP) {
            const __nv_bfloat16* src = (p ? Vl_ : Vh_) + (size_t)(b*Ss + f*NSP + kk)*Dd + h*64 + ch*8;
            v = *(const uint4*)src;
        }
        *(uint4*)(sm + (p ? S1_OVL : S1_OVH) + kk*144 + ch*16) = v;
    }
    __syncthreads();

    const int ra = (lane & 7) + ((lane >> 3) & 1) * 8;
    const int ca = (lane >> 4) & 1;
    const int rb = (lane & 7) + ((lane >> 4) & 1) * 8;
    const int cb = (lane >> 3) & 1;

    float c[2][13][4];
#pragma unroll
    for (int i = 0; i < 2; i++)
#pragma unroll
        for (int j = 0; j < 13; j++)
#pragma unroll
            for (int e = 0; e < 4; e++) c[i][j][e] = 0.f;

    {
        uint32_t aQh = sb + S1_OQH + (wm*32 + ra)*144 + ca*16;
        uint32_t aQl = sb + S1_OQL + (wm*32 + ra)*144 + ca*16;
        uint32_t aKh = sb + S1_OKH + (wn*104 + rb)*144 + cb*16;
        uint32_t aKl = sb + S1_OKL + (wn*104 + rb)*144 + cb*16;
#pragma unroll
        for (int ks = 0; ks < 4; ks++) {
            uint32_t ah[2][4], al[2][4], bh_[7][4], bl_[7][4];
            ldmx4(ah[0], aQh + ks*32);
            ldmx4(ah[1], aQh + 16*144 + ks*32);
            ldmx4(al[0], aQl + ks*32);
            ldmx4(al[1], aQl + 16*144 + ks*32);
#pragma unroll
            for (int j = 0; j < 7; j++) {
                ldmx4(bh_[j], aKh + j*16*144 + ks*32);
                ldmx4(bl_[j], aKl + j*16*144 + ks*32);
            }
#pragma unroll
            for (int mi = 0; mi < 2; mi++)
#pragma unroll
                for (int nj = 0; nj < 13; nj++) {
                    const uint32_t* bhp = &bh_[nj >> 1][(nj & 1) * 2];
                    const uint32_t* blp = &bl_[nj >> 1][(nj & 1) * 2];
                    mma_bf16(c[mi][nj], ah[mi], bhp);
                    mma_bf16(c[mi][nj], al[mi], bhp);
                    mma_bf16(c[mi][nj], ah[mi], blp);
                }
        }
    }

    float* rmax = (float*)(sm + S1_ORMAX);
    float* rsum = (float*)(sm + S1_ORSUM);
    const int qr = lane >> 2, qc = (lane & 3) * 2;

    float mx[2][2] = {{-1e30f,-1e30f},{-1e30f,-1e30f}};
#pragma unroll
    for (int mi = 0; mi < 2; mi++)
#pragma unroll
        for (int nj = 0; nj < 13; nj++) {
            int col = wn*104 + nj*8 + qc;
            if (col < NSP) {
#pragma unroll
                for (int hf = 0; hf < 2; hf++)
                    mx[mi][hf] = fmaxf(mx[mi][hf], fmaxf(c[mi][nj][hf*2], c[mi][nj][hf*2+1]));
            }
        }
#pragma unroll
    for (int mi = 0; mi < 2; mi++)
#pragma unroll
        for (int hf = 0; hf < 2; hf++) {
            float m = mx[mi][hf];
            m = fmaxf(m, __shfl_xor_sync(0xffffffffu, m, 1));
            m = fmaxf(m, __shfl_xor_sync(0xffffffffu, m, 2));
            if ((lane & 3) == 0)
                rmax[wn*128 + wm*32 + mi*16 + qr + hf*8] = m;
        }
    __syncthreads();

    float Mv[2][2], sum_[2][2] = {{0,0},{0,0}};
#pragma unroll
    for (int mi = 0; mi < 2; mi++)
#pragma unroll
        for (int hf = 0; hf < 2; hf++) {
            int row = wm*32 + mi*16 + qr + hf*8;
            Mv[mi][hf] = fmaxf(rmax[row], rmax[128 + row]);
        }
#pragma unroll
    for (int mi = 0; mi < 2; mi++)
#pragma unroll
        for (int nj = 0; nj < 13; nj++) {
            int col = wn*104 + nj*8 + qc;
            bool valid = col < NSP;
#pragma unroll
            for (int hf = 0; hf < 2; hf++) {
                float e0 = valid ? __expf(SCALE*(c[mi][nj][hf*2]   - Mv[mi][hf])) : 0.f;
                float e1 = valid ? __expf(SCALE*(c[mi][nj][hf*2+1] - Mv[mi][hf])) : 0.f;
                c[mi][nj][hf*2]   = e0;
                c[mi][nj][hf*2+1] = e1;
                sum_[mi][hf] += e0 + e1;
            }
        }
#pragma unroll
    for (int mi = 0; mi < 2; mi++)
#pragma unroll
        for (int hf = 0; hf < 2; hf++) {
            float s = sum_[mi][hf];
            s += __shfl_xor_sync(0xffffffffu, s, 1);
            s += __shfl_xor_sync(0xffffffffu, s, 2);
            if ((lane & 3) == 0)
                rsum[wn*128 + wm*32 + mi*16 + qr + hf*8] = s;
        }
    __syncthreads();

#pragma unroll
    for (int mi = 0; mi < 2; mi++)
#pragma unroll
        for (int hf = 0; hf < 2; hf++) {
            int row = wm*32 + mi*16 + qr + hf*8;
            int qg  = q0g + row;
            float inv = 1.f / (rsum[row] + rsum[128 + row]);
            bool rowv = qg < Ss;
            float* sap = rowv ? &SA[((size_t)(bh*Ss + qg)*Ff + f)*NSP] : nullptr;
#pragma unroll
            for (int nj = 0; nj < 13; nj++) {
                int col = wn*104 + nj*8 + qc;
                float p0 = c[mi][nj][hf*2]   * inv;
                float p1 = c[mi][nj][hf*2+1] * inv;
                if (rowv && col < NSP)
                    *(float2*)&sap[col] = make_float2(p0, p1);
                uint32_t hb, lb;
                split2(p0, p1, hb, lb);
                *(uint32_t*)(sm + S1_OPH + row*464 + col*2) = hb;
                *(uint32_t*)(sm + S1_OPL + row*464 + col*2) = lb;
            }
        }
    for (int t = tid; t < 768; t += 256) {
        int p = t / 384, rem = t % 384;
        int rr = rem / 3, j = rem % 3;
        *(uint4*)(sm + (p ? S1_OPL : S1_OPH) + rr*464 + 416 + j*16) = make_uint4(0,0,0,0);
    }
    __syncthreads();

    float c2[2][4][4];
#pragma unroll
    for (int i = 0; i < 2; i++)
#pragma unroll
        for (int j = 0; j < 4; j++)
#pragma unroll
            for (int e = 0; e < 4; e++) c2[i][j][e] = 0.f;

    {
        const int rv = (lane & 7) + ((lane >> 3) & 1) * 8;
        const int cv = (lane >> 4) & 1;
        uint32_t aPh = sb + S1_OPH + (wm*32 + ra)*464 + ca*16;
        uint32_t aPl = sb + S1_OPL + (wm*32 + ra)*464 + ca*16;
        uint32_t aVh = sb + S1_OVH + rv*144 + (wn*32)*2 + cv*16;
        uint32_t aVl = sb + S1_OVL + rv*144 + (wn*32)*2 + cv*16;
#pragma unroll
        for (int ks = 0; ks < 14; ks++) {
            uint32_t ph[2][4], pl[2][4], vh[2][4], vl[2][4];
            ldmx4(ph[0], aPh + ks*32);
            ldmx4(ph[1], aPh + 16*464 + ks*32);
            ldmx4(pl[0], aPl + ks*32);
            ldmx4(pl[1], aPl + 16*464 + ks*32);
            ldmx4t(vh[0], aVh + ks*16*144);
            ldmx4t(vh[1], aVh + ks*16*144 + 32);
            ldmx4t(vl[0], aVl + ks*16*144);
            ldmx4t(vl[1], aVl + ks*16*144 + 32);
#pragma unroll
            for (int mi = 0; mi < 2; mi++)
#pragma unroll
                for (int nj = 0; nj < 4; nj++) {
                    const uint32_t* bhp = &vh[nj >> 1][(nj & 1) * 2];
                    const uint32_t* blp = &vl[nj >> 1][(nj & 1) * 2];
                    mma_bf16(c2[mi][nj], ph[mi], bhp);
                    mma_bf16(c2[mi][nj], pl[mi], bhp);
                    mma_bf16(c2[mi][nj], ph[mi], blp);
                }
        }
    }

#pragma unroll
    for (int mi = 0; mi < 2; mi++)
#pragma unroll
        for (int hf = 0; hf < 2; hf++) {
            int row = wm*32 + mi*16 + qr + hf*8;
            int qg  = q0g + row;
            if (qg >= Ss) continue;
            size_t base = ((size_t)(b*Ss + qg)*Ff + f)*Dd + h*64;
#pragma unroll
            for (int nj = 0; nj < 4; nj++) {
                int col = wn*32 + nj*8 + qc;
                uint32_t hb, lb;
                split2(c2[mi][nj][hf*2], c2[mi][nj][hf*2+1], hb, lb);
                *(uint32_t*)&XH[base + col] = hb;
                *(uint32_t*)&XL[base + col] = lb;
            }
        }
}

// ============================================================
// Diagonal gather on bf16 planes
// ============================================================
__global__ void diag_kernel(const uint2* __restrict__ XH, const uint2* __restrict__ XL,
                            uint2* __restrict__ XDH, uint2* __restrict__ XDL)
{
    int idx = blockIdx.x * blockDim.x + threadIdx.x;
    if (idx >= BSD/4) return;
    int c4   = idx % (Dd/4);
    int rest = idx / (Dd/4);
    int s = rest % Ss;
    int b = rest / Ss;
    int f = s / NSP;
    size_t src = ((size_t)(b*Ss + s)*Ff + f)*(Dd/4) + c4;
    XDH[idx] = XH[src];
    XDL[idx] = XL[src];
}

// ============================================================
// traj: per token — logits from x·m + q2·bk2, softmax over F,
// xw[h] = sum_f attn*x_f -> bf16 planes
// ============================================================
__global__ __launch_bounds__(128) void traj_kernel(
    const __nv_bfloat16* __restrict__ xh, const __nv_bfloat16* __restrict__ xl,
    const __nv_bfloat16* __restrict__ q2h, const __nv_bfloat16* __restrict__ q2l,
    const float* __restrict__ M_, const float* __restrict__ bpkv,
    __nv_bfloat16* __restrict__ xwh, __nv_bfloat16* __restrict__ xwl)
{
    __shared__ float xs[Ff][768];
    __shared__ float bq[Hh];
    const int t = blockIdx.x;
    const int tid = threadIdx.x;
    const int wid = tid >> 5, lane = tid & 31;

    {
        const uint4* ph = (const uint4*)(xh + (size_t)t*Ff*768);
        const uint4* pl = (const uint4*)(xl + (size_t)t*Ff*768);
        for (int i = tid; i < 768; i += 128) {
            uint4 vh = ph[i], vl = pl[i];
            int f = (i * 8) / 768, j = (i * 8) % 768;
            const uint32_t* wh = (const uint32_t*)&vh;
            const uint32_t* wl = (const uint32_t*)&vl;
#pragma unroll
            for (int w = 0; w < 4; w++) {
                float2 fh = __bfloat1622float2(*(const __nv_bfloat162*)&wh[w]);
                float2 fl = __bfloat1622float2(*(const __nv_bfloat162*)&wl[w]);
                xs[f][j + w*2 + 0] = fh.x + fl.x;
                xs[f][j + w*2 + 1] = fh.y + fl.y;
            }
        }
    }
#pragma unroll
    for (int hh = 0; hh < 3; hh++) {
        int h = wid * 3 + hh;
        int d0 = h*64 + lane;
        float qa = __bfloat162float(q2h[(size_t)t*768 + d0])      + __bfloat162float(q2l[(size_t)t*768 + d0]);
        float qb = __bfloat162float(q2h[(size_t)t*768 + d0 + 32]) + __bfloat162float(q2l[(size_t)t*768 + d0 + 32]);
        float acc = qa * bpkv[d0] + qb * bpkv[d0 + 32];
#pragma unroll
        for (int o = 16; o > 0; o >>= 1) acc += __shfl_xor_sync(0xffffffffu, acc, o);
        if (lane == 0) bq[h] = acc;
    }
    __syncthreads();

#pragma unroll
    for (int hh = 0; hh < 3; hh++) {
        int h = wid * 3 + hh;
        const float* mh = M_ + (size_t)t*(Hh*768) + (size_t)h*768;
        float acc[Ff];
#pragma unroll
        for (int f = 0; f < Ff; f++) acc[f] = 0.f;
        for (int js = 0; js < 24; js++) {
            int j = js*32 + lane;
            float mv = mh[j];
#pragma unroll
            for (int f = 0; f < Ff; f++) acc[f] += xs[f][j] * mv;
        }
        float lg[Ff];
#pragma unroll
        for (int f = 0; f < Ff; f++) {
            float s = acc[f];
#pragma unroll
            for (int o = 16; o > 0; o >>= 1) s += __shfl_xor_sync(0xffffffffu, s, o);
            lg[f] = SCALE * (s + bq[h]);
        }
        float mm = lg[0];
#pragma unroll
        for (int f = 1; f < Ff; f++) mm = fmaxf(mm, lg[f]);
        float attn[Ff], sum = 0.f;
#pragma unroll
        for (int f = 0; f < Ff; f++) { attn[f] = __expf(lg[f] - mm); sum += attn[f]; }
        float inv = 1.f / sum;
#pragma unroll
        for (int f = 0; f < Ff; f++) attn[f] *= inv;

        size_t base = (size_t)t*(Hh*768) + (size_t)h*768;
        for (int i = 0; i < 12; i++) {
            int j0 = i*64 + lane*2;
            float a0 = 0.f, a1 = 0.f;
#pragma unroll
            for (int f = 0; f < Ff; f++) {
                a0 += attn[f] * xs[f][j0];
                a1 += attn[f] * xs[f][j0 + 1];
            }
            uint32_t hb, lb;
            split2(a0, a1, hb, lb);
            *(uint32_t*)&xwh[base + j0] = hb;
            *(uint32_t*)&xwl[base + j0] = lb;
        }
    }
}

// ============================================================
// launch
// ============================================================
extern "C" void kernel_launch(void* const* d_in, const int* in_sizes, int n_in,
                              void* d_out, int out_size)
{
    const float* query = (const float*)d_in[0];
    const float* key_t = (const float*)d_in[1];
    const float* value = (const float*)d_in[2];
    const float* Wq   = (const float*)d_in[3];
    const float* bq   = (const float*)d_in[4];
    const float* Wk   = (const float*)d_in[5];
    const float* bk   = (const float*)d_in[6];
    const float* Wv   = (const float*)d_in[7];
    const float* bv   = (const float*)d_in[8];
    const float* Wpq  = (const float*)d_in[9];
    const float* bpq  = (const float*)d_in[10];
    const float* Wpkv = (const float*)d_in[11];
    const float* bpkv = (const float*)d_in[12];
    const float* Wp   = (const float*)d_in[13];
    const float* bp   = (const float*)d_in[14];

    float* out = (float*)d_out;            // (B, S, D)
    float* sa  = out + BSD;                // (B*H, S, F, n)

    float *mbuf, *zerob, *bqkv;
    __nv_bfloat16 *wth, *wtl, *wk2h, *wk2l;
    __nv_bfloat16 *inh, *inl, *qkvh, *qkvl;
    __nv_bfloat16 *xh, *xl, *xdh, *xdl, *q2h, *q2l, *xwh, *xwl, *t2h, *t2l;
    cudaGetSymbolAddress((void**)&mbuf, g_m);
    cudaGetSymbolAddress((void**)&zerob, g_zerob);
    cudaGetSymbolAddress((void**)&bqkv, g_bqkv);
    cudaGetSymbolAddress((void**)&wth, g_wth);
    cudaGetSymbolAddress((void**)&wtl, g_wtl);
    cudaGetSymbolAddress((void**)&wk2h, g_wk2h);
    cudaGetSymbolAddress((void**)&wk2l, g_wk2l);
    cudaGetSymbolAddress((void**)&inh, g_inh);
    cudaGetSymbolAddress((void**)&inl, g_inl);
    cudaGetSymbolAddress((void**)&qkvh, g_qkvh);
    cudaGetSymbolAddress((void**)&qkvl, g_qkvl);
    cudaGetSymbolAddress((void**)&xh,  g_xh);
    cudaGetSymbolAddress((void**)&xl,  g_xl);
    cudaGetSymbolAddress((void**)&xdh, g_xdh);
    cudaGetSymbolAddress((void**)&xdl, g_xdl);
    cudaGetSymbolAddress((void**)&q2h, g_q2h);
    cudaGetSymbolAddress((void**)&q2l, g_q2l);
    cudaGetSymbolAddress((void**)&xwh, g_xwh);
    cudaGetSymbolAddress((void**)&xwl, g_xwl);
    cudaGetSymbolAddress((void**)&t2h, g_t2h);
    cudaGetSymbolAddress((void**)&t2l, g_t2l);

    cudaFuncSetAttribute(stage1_mma_kernel,
                         cudaFuncAttributeMaxDynamicSharedMemorySize, S1_SMEM);
    cudaFuncSetAttribute(gemm_tpl<0,128>,
                         cudaFuncAttributeMaxDynamicSharedMemorySize, SMEM_128);
    cudaFuncSetAttribute(gemm_tpl<1,128>,
                         cudaFuncAttributeMaxDynamicSharedMemorySize, SMEM_128);
    cudaFuncSetAttribute(gemm_tpl<1,64>,
                         cudaFuncAttributeMaxDynamicSharedMemorySize, SMEM_64);
    cudaFuncSetAttribute(gemm_tpl<0,64>,
                         cudaFuncAttributeMaxDynamicSharedMemorySize, SMEM_64);

    int n4 = BSD/4, sg = (n4 + 255)/256;
    dim3 wb(32, 8);

    // launches 0-2: wtrans for Wq, Wk, Wv (needed by projection)
    wtrans_kernel<<<dim3(24,24), wb>>>(Wq, wth+OFF_WQ, wtl+OFF_WQ, 768, 768);
    wtrans_kernel<<<dim3(24,24), wb>>>(Wk, wth+OFF_WK, wtl+OFF_WK, 768, 768);
    wtrans_kernel<<<dim3(24,24), wb>>>(Wv, wth+OFF_WV, wtl+OFF_WV, 768, 768);
    // launch 3: merged input split
    split3_kernel<<<dim3(sg,3), 256>>>((const float4*)query, (const float4*)key_t,
                                       (const float4*)value, (uint2*)inh, (uint2*)inl, n4);
    // launch 4: bias pack
    biaspack_kernel<<<9, 256>>>(bq, bk, bv, bqkv);

    // launch 5 (ncu capture target): merged q/k/v projection, grid z=3 -> 450 CTAs
    gemm_tpl<1,128><<<dim3(6,25,3), 256, SMEM_128>>>(
        inh, inl, 768, (long)BSD,
        wth+OFF_WQ, wtl+OFF_WQ, 768, (long)WSQ,
        bqkv, 768,
        nullptr, qkvh, qkvl, 768, (long)BSD,
        BS, 768);

    // remaining weight prep (independent of projections)
    wtrans_kernel<<<dim3(24,24), wb>>>(Wpq, wth+OFF_WPQ, wtl+OFF_WPQ, 768, 768);
    wtrans_kernel<<<dim3(24,24), wb>>>(Wp,  wth+OFF_WP,  wtl+OFF_WP,  768, 768);
    wtrans_kernel<<<dim3(48,24), wb>>>(Wpkv, wth+OFF_WPKV, wtl+OFF_WPKV, 768, 1536);
    splitwk2_kernel<<<(768*192 + 255)/256, 256>>>(Wpkv, wk2h, wk2l);

    stage1_mma_kernel<<<dim3(13, Ff, Bb*Hh), 256, S1_SMEM>>>(
        qkvh, qkvl, qkvh + BSD, qkvl + BSD, qkvh + 2*BSD, qkvl + 2*BSD, xh, xl, sa);

    diag_kernel<<<(BSD/4 + 255)/256, 256>>>(
        (const uint2*)xh, (const uint2*)xl, (uint2*)xdh, (uint2*)xdl);

    // q2 = xd @ Wpq + bpq  (split output), NTILE=64 -> 300 CTAs (balanced)
    gemm_tpl<1,64><<<dim3(12, 25, 1), 256, SMEM_64>>>(
        xdh, xdl, 768, 0, wth+OFF_WPQ, wtl+OFF_WPQ, 768, 0,
        bpq, 0, nullptr, q2h, q2l, 768, 0, BS, 768);

    // m[t,h,:] = Wk2[:,hslice] @ q2_h : per-head GEMM M=BS, N=768, K=64
    gemm_tpl<0,128><<<dim3(6, 25, 12), 256, SMEM_128>>>(
        q2h, q2l, 768, 64,
        wk2h, wk2l, 768, 64,
        zerob, 0,
        mbuf, nullptr, nullptr, Hh*768, 768,
        BS, 64);

    // logits + softmax + xw
    traj_kernel<<<BS, 128>>>(xh, xl, q2h, q2l, mbuf, bpkv, xwh, xwl);

    // o_h = xw_h @ Wv2[:,hslice] + bv2_h : per-head GEMM M=BS, N=64, K=768 -> t2 planes
    gemm_tpl<1,64><<<dim3(1, 25, 12), 256, SMEM_64>>>(
        xwh, xwl, Hh*768, 768,
        wth + OFF_WPKV + (size_t)768*768, wtl + OFF_WPKV + (size_t)768*768, 768, (long)64*768,
        bpkv + 768, 64,
        nullptr, t2h, t2l, 768, 64,
        BS, 768);

    // out = t2 @ Wp + bp, NTILE=64 -> 300 CTAs (balanced)
    gemm_tpl<0,64><<<dim3(12, 25, 1), 256, SMEM_64>>>(
        t2h, t2l, 768, 0, wth+OFF_WP, wtl+OFF_WP, 768, 0,
        bp, 0, out, nullptr, nullptr, 768, 0, BS, 768);
}

// round 13
// speedup vs baseline: 1.0367x; 1.0367x over previous
#include <cuda_runtime.h>
#include <cuda_bf16.h>
#include <cstdint>
#include <cstddef>

// ---- problem constants ----
#define Bb   2
#define Ss   1568
#define Dd   768
#define Hh   12
#define HDd  64
#define Ff   8
#define NSP  196
#define BS   (Bb*Ss)             // 3136
#define BSD  (Bb*Ss*Dd)          // 2408448
#define XSZ  (Bb*Ss*Ff*Dd)       // 19267584
#define SCALE 0.125f

// ---- scratch ----
__device__ float g_m[(size_t)BS*Hh*Dd];      // [t][h][768] fp32 logit-matrices
__device__ float g_zerob[768];               // zero bias (static-zeroed)
__device__ float g_bqkv[3*768];              // packed bq|bk|bv

// bf16 hi/lo planes (contiguous for batched GEMMs)
__device__ __align__(16) __nv_bfloat16 g_inh[3*BSD], g_inl[3*BSD];     // query|key|value split
__device__ __align__(16) __nv_bfloat16 g_qkvh[3*BSD], g_qkvl[3*BSD];   // projected q|k|v
__device__ __align__(16) __nv_bfloat16 g_xh [XSZ], g_xl [XSZ];
__device__ __align__(16) __nv_bfloat16 g_xdh[BSD], g_xdl[BSD];
__device__ __align__(16) __nv_bfloat16 g_q2h[BSD], g_q2l[BSD];
__device__ __align__(16) __nv_bfloat16 g_xwh[(size_t)BS*Hh*Dd], g_xwl[(size_t)BS*Hh*Dd];
__device__ __align__(16) __nv_bfloat16 g_t2h[BSD], g_t2l[BSD];
__device__ __align__(16) __nv_bfloat16 g_wk2h[768*768], g_wk2l[768*768]; // Wpkv[:, :768] row-major split

// transposed+split weights: [N][K] bf16, hi and lo parts
#define WSQ  (768*768)
#define OFF_WQ   0
#define OFF_WK   (1*WSQ)
#define OFF_WV   (2*WSQ)
#define OFF_WPQ  (3*WSQ)
#define OFF_WP   (4*WSQ)
#define OFF_WPKV (5*WSQ)
#define WT_ELEMS (5*WSQ + 1536*768)
__device__ __align__(16) __nv_bfloat16 g_wth[WT_ELEMS];
__device__ __align__(16) __nv_bfloat16 g_wtl[WT_ELEMS];

// ============================================================
// helpers
// ============================================================
__device__ __forceinline__ uint32_t smem_u32(const void* p) {
    uint32_t a;
    asm("{ .reg .u64 t; cvta.to.shared.u64 t, %1; cvt.u32.u64 %0, t; }" : "=r"(a) : "l"(p));
    return a;
}
__device__ __forceinline__ void ldmx4(uint32_t* r, uint32_t a) {
    asm volatile("ldmatrix.sync.aligned.m8n8.x4.shared.b16 {%0,%1,%2,%3}, [%4];"
        : "=r"(r[0]), "=r"(r[1]), "=r"(r[2]), "=r"(r[3]) : "r"(a));
}
__device__ __forceinline__ void ldmx4t(uint32_t* r, uint32_t a) {
    asm volatile("ldmatrix.sync.aligned.m8n8.x4.trans.shared.b16 {%0,%1,%2,%3}, [%4];"
        : "=r"(r[0]), "=r"(r[1]), "=r"(r[2]), "=r"(r[3]) : "r"(a));
}
__device__ __forceinline__ void mma_bf16(float* c, const uint32_t* a, const uint32_t* b) {
    asm volatile("mma.sync.aligned.m16n8k16.row.col.f32.bf16.bf16.f32 "
        "{%0,%1,%2,%3}, {%4,%5,%6,%7}, {%8,%9}, {%0,%1,%2,%3};"
        : "+f"(c[0]), "+f"(c[1]), "+f"(c[2]), "+f"(c[3])
        : "r"(a[0]), "r"(a[1]), "r"(a[2]), "r"(a[3]), "r"(b[0]), "r"(b[1]));
}
#define CP_ASYNC16(dst, src, sz) \
    asm volatile("cp.async.cg.shared.global [%0], [%1], 16, %2;" \
                 :: "r"(dst), "l"(src), "r"(sz))
#define CP_COMMIT() asm volatile("cp.async.commit_group;" ::: "memory")
#define CP_WAIT(n)  asm volatile("cp.async.wait_group %0;" :: "n"(n) : "memory")

__device__ __forceinline__ void split2(float a, float b, uint32_t& h, uint32_t& l) {
    __nv_bfloat162 hh = __floats2bfloat162_rn(a, b);
    float2 f = __bfloat1622float2(hh);
    __nv_bfloat162 ll = __floats2bfloat162_rn(a - f.x, b - f.y);
    h = *(uint32_t*)&hh; l = *(uint32_t*)&ll;
}

// ============================================================
// merged weight transpose+split for Wq|Wk|Wv via grid.z
// ============================================================
__global__ void wtrans3_kernel(const float* __restrict__ W0, const float* __restrict__ W1,
                               const float* __restrict__ W2,
                               __nv_bfloat16* __restrict__ hi, __nv_bfloat16* __restrict__ lo)
{
    __shared__ float t[32][33];
    const float* W = blockIdx.z == 0 ? W0 : (blockIdx.z == 1 ? W1 : W2);
    size_t wo = (size_t)blockIdx.z * WSQ;
    int n0 = blockIdx.x * 32, k0 = blockIdx.y * 32;
    int tx = threadIdx.x, ty = threadIdx.y;
#pragma unroll
    for (int i = 0; i < 32; i += 8)
        t[ty + i][tx] = W[(size_t)(k0 + ty + i) * 768 + n0 + tx];
    __syncthreads();
#pragma unroll
    for (int i = 0; i < 32; i += 8) {
        float v = t[tx][ty + i];
        __nv_bfloat16 h = __float2bfloat16(v);
        __nv_bfloat16 l = __float2bfloat16(v - __bfloat162float(h));
        size_t o = wo + (size_t)(n0 + ty + i) * 768 + k0 + tx;
        hi[o] = h; lo[o] = l;
    }
}

__global__ void wtrans_kernel(const float* __restrict__ W,
                              __nv_bfloat16* __restrict__ hi,
                              __nv_bfloat16* __restrict__ lo, int K, int N)
{
    __shared__ float t[32][33];
    int n0 = blockIdx.x * 32, k0 = blockIdx.y * 32;
    int tx = threadIdx.x, ty = threadIdx.y;
#pragma unroll
    for (int i = 0; i < 32; i += 8)
        t[ty + i][tx] = W[(size_t)(k0 + ty + i) * N + n0 + tx];
    __syncthreads();
#pragma unroll
    for (int i = 0; i < 32; i += 8) {
        float v = t[tx][ty + i];
        __nv_bfloat16 h = __float2bfloat16(v);
        __nv_bfloat16 l = __float2bfloat16(v - __bfloat162float(h));
        size_t o = (size_t)(n0 + ty + i) * K + k0 + tx;
        hi[o] = h; lo[o] = l;
    }
}

// ============================================================
// merged elementwise fp32 -> bf16 hi/lo planes (3 inputs via grid.y)
// ============================================================
__global__ void split3_kernel(const float4* __restrict__ a0, const float4* __restrict__ a1,
                              const float4* __restrict__ a2,
                              uint2* __restrict__ H, uint2* __restrict__ L, int n4)
{
    int i = blockIdx.x * blockDim.x + threadIdx.x;
    if (i >= n4) return;
    int which = blockIdx.y;
    const float4* in = which == 0 ? a0 : (which == 1 ? a1 : a2);
    float4 a = in[i];
    uint32_t h01, l01, h23, l23;
    split2(a.x, a.y, h01, l01);
    split2(a.z, a.w, h23, l23);
    size_t o = (size_t)which * n4 + i;
    H[o] = make_uint2(h01, h23);
    L[o] = make_uint2(l01, l23);
}

__global__ void biaspack_kernel(const float* __restrict__ b0, const float* __restrict__ b1,
                                const float* __restrict__ b2, float* __restrict__ dst)
{
    int i = blockIdx.x * blockDim.x + threadIdx.x;
    if (i >= 3*768) return;
    int w = i / 768, j = i % 768;
    dst[i] = (w == 0 ? b0 : (w == 1 ? b1 : b2))[j];
}

__global__ void splitwk2_kernel(const float* __restrict__ Wpkv,
                                __nv_bfloat16* __restrict__ H, __nv_bfloat16* __restrict__ L)
{
    int i = blockIdx.x * blockDim.x + threadIdx.x;
    if (i >= 768*192) return;
    int j = i / 192, c4 = (i % 192) * 4;
    float4 a = *(const float4*)&Wpkv[(size_t)j * 1536 + c4];
    uint32_t h01, l01, h23, l23;
    split2(a.x, a.y, h01, l01);
    split2(a.z, a.w, h23, l23);
    *(uint2*)&H[(size_t)j*768 + c4] = make_uint2(h01, h23);
    *(uint2*)&L[(size_t)j*768 + c4] = make_uint2(l01, l23);
}

// ============================================================
// HMMA bf16x3 GEMM, templated: NTILE in {128, 64}, OUT_SPLIT in {0,1}
// ============================================================
template <int OUT_SPLIT, int NTILE>
__device__ __forceinline__ void gemm_body(
    const __nv_bfloat16* __restrict__ Ah, const __nv_bfloat16* __restrict__ Al, int lda,
    const __nv_bfloat16* __restrict__ Bh, const __nv_bfloat16* __restrict__ Bl, int ldb,
    const float* __restrict__ bias,
    float* __restrict__ C, __nv_bfloat16* __restrict__ CH, __nv_bfloat16* __restrict__ CL,
    int ldc, int M, int K)
{
    constexpr int NJ  = NTILE / 16;
    constexpr int BST = NTILE * 80;
    constexpr int STG = 20480 + 2 * BST;
    constexpr int CPN = 1024 + NTILE * 8;

    extern __shared__ char smem[];
    const uint32_t sb = smem_u32(smem);
    const int tid = threadIdx.x;
    const int wid = tid >> 5, lane = tid & 31;
    const int bm = blockIdx.y * 128, bn = blockIdx.x * NTILE;
    const int m0 = (wid & 3) * 32;
    const int n0 = (wid >> 2) * (NTILE / 2);

    float c[2][NJ][4];
#pragma unroll
    for (int i = 0; i < 2; i++)
#pragma unroll
        for (int j = 0; j < NJ; j++)
#pragma unroll
            for (int e = 0; e < 4; e++) c[i][j][e] = 0.f;

    const int ra = (lane & 7) + ((lane >> 3) & 1) * 8;
    const int ca = (lane >> 4) & 1;
    const int rb = (lane & 7) + ((lane >> 4) & 1) * 8;
    const int cb = (lane >> 3) & 1;

    auto issue = [&](int kb, int s) {
        for (int i = tid; i < CPN; i += 256) {
            uint32_t dst, sz = 16;
            const __nv_bfloat16* src;
            if (i < 1024) {
                int p = i >> 9, rem = i & 511;
                int row = rem >> 2, c4 = rem & 3;
                dst = sb + s * STG + p * 10240 + row * 80 + c4 * 16;
                int gm = bm + row;
                int g  = gm < M ? gm : 0;
                if (gm >= M) sz = 0;
                src = (p == 0 ? Ah : Al) + (size_t)g * lda + kb + c4 * 8;
            } else {
                int i2 = i - 1024;
                int p = i2 / (NTILE * 4), rem = i2 % (NTILE * 4);
                int row = rem >> 2, c4 = rem & 3;
                dst = sb + s * STG + 20480 + p * BST + row * 80 + c4 * 16;
                src = (p == 0 ? Bh : Bl) + (size_t)(bn + row) * ldb + kb + c4 * 8;
            }
            CP_ASYNC16(dst, src, sz);
        }
    };

    issue(0, 0);
    CP_COMMIT();

    int s = 0;
    for (int kb = 0; kb < K; kb += 32, s ^= 1) {
        if (kb + 32 < K) {
            issue(kb + 32, s ^ 1);
            CP_COMMIT();
            CP_WAIT(1);
        } else {
            CP_WAIT(0);
        }
        __syncthreads();

        uint32_t base = sb + s * STG;
        uint32_t aAh = base +     0 + (m0 + ra) * 80 + ca * 16;
        uint32_t aAl = base + 10240 + (m0 + ra) * 80 + ca * 16;
        uint32_t aBh = base + 20480 +       (n0 + rb) * 80 + cb * 16;
        uint32_t aBl = base + 20480 + BST + (n0 + rb) * 80 + cb * 16;

#pragma unroll
        for (int ks = 0; ks < 2; ks++) {
            uint32_t ah[2][4], al[2][4], bh[NJ/2][4], bl[NJ/2][4];
            ldmx4(ah[0], aAh + ks * 32);
            ldmx4(ah[1], aAh + 16 * 80 + ks * 32);
            ldmx4(al[0], aAl + ks * 32);
            ldmx4(al[1], aAl + 16 * 80 + ks * 32);
#pragma unroll
            for (int j = 0; j < NJ/2; j++) {
                ldmx4(bh[j], aBh + j * 16 * 80 + ks * 32);
                ldmx4(bl[j], aBl + j * 16 * 80 + ks * 32);
            }
#pragma unroll
            for (int mi = 0; mi < 2; mi++)
#pragma unroll
                for (int nj = 0; nj < NJ; nj++) {
                    const uint32_t* bhp = &bh[nj >> 1][(nj & 1) * 2];
                    const uint32_t* blp = &bl[nj >> 1][(nj & 1) * 2];
                    mma_bf16(c[mi][nj], ah[mi], bhp);
                    mma_bf16(c[mi][nj], al[mi], bhp);
                    mma_bf16(c[mi][nj], ah[mi], blp);
                }
        }
        __syncthreads();
    }

    const int cr = lane >> 2, cc = (lane & 3) * 2;
#pragma unroll
    for (int nj = 0; nj < NJ; nj++) {
        int bcol = bn + n0 + nj * 8 + cc;
        float b0 = bias[bcol], b1 = bias[bcol + 1];
#pragma unroll
        for (int mi = 0; mi < 2; mi++) {
#pragma unroll
            for (int hf = 0; hf < 2; hf++) {
                int r = bm + m0 + mi * 16 + cr + hf * 8;
                if (r >= M) continue;
                float o0 = c[mi][nj][hf*2+0] + b0;
                float o1 = c[mi][nj][hf*2+1] + b1;
                if (OUT_SPLIT) {
                    uint32_t h, l;
                    split2(o0, o1, h, l);
                    *(uint32_t*)&CH[(size_t)r * ldc + bcol] = h;
                    *(uint32_t*)&CL[(size_t)r * ldc + bcol] = l;
                } else {
                    *(float2*)&C[(size_t)r * ldc + bcol] = make_float2(o0, o1);
                }
            }
        }
    }
}

template <int OUT_SPLIT, int NTILE>
__global__ __launch_bounds__(256) void gemm_tpl(
    const __nv_bfloat16* Ah, const __nv_bfloat16* Al, int lda, long aZ,
    const __nv_bfloat16* Bh, const __nv_bfloat16* Bl, int ldb, long bZ,
    const float* bias, long biasZ,
    float* C, __nv_bfloat16* CH, __nv_bfloat16* CL, int ldc, long cZ,
    int M, int K)
{
    long z = blockIdx.z;
    gemm_body<OUT_SPLIT, NTILE>(
        Ah + z*aZ, Al + z*aZ, lda,
        Bh + z*bZ, Bl + z*bZ, ldb,
        bias + z*biasZ,
        C  ? C  + z*cZ : nullptr,
        CH ? CH + z*cZ : nullptr,
        CL ? CL + z*cZ : nullptr,
        ldc, M, K);
}

#define SMEM_128 81920
#define SMEM_64  61440

// ============================================================
// Stage 1 (HMMA): per (b,h,f, 128-query tile) fused attention.
// K/V: 208 rows loaded (196 real + 12 zero); P cols 0..207; PV 13 ksteps.
// ============================================================
#define S1_OPH   0
#define S1_OPL   59392
#define S1_OQH   0
#define S1_OQL   18432
#define S1_OKH   36864
#define S1_OKL   69120
#define S1_OVH   118784
#define S1_OVL   151040
#define S1_ORMAX 183296
#define S1_ORSUM 184320
#define S1_SMEM  185344

__global__ __launch_bounds__(256) void stage1_mma_kernel(
    const __nv_bfloat16* __restrict__ Qh_, const __nv_bfloat16* __restrict__ Ql_,
    const __nv_bfloat16* __restrict__ Kh_, const __nv_bfloat16* __restrict__ Kl_,
    const __nv_bfloat16* __restrict__ Vh_, const __nv_bfloat16* __restrict__ Vl_,
    __nv_bfloat16* __restrict__ XH, __nv_bfloat16* __restrict__ XL,
    float* __restrict__ SA)
{
    extern __shared__ char sm[];
    const uint32_t sb = smem_u32(sm);
    const int tid = threadIdx.x;
    const int wid = tid >> 5, lane = tid & 31;
    const int wm = wid & 3, wn = wid >> 2;
    const int q0g = blockIdx.x * 128;
    const int f   = blockIdx.y;
    const int bh  = blockIdx.z;
    const int b   = bh / Hh, h = bh % Hh;

    for (int t = tid; t < 2048; t += 256) {
        int p = t >> 10, r = (t >> 3) & 127, ch = t & 7;
        int qg = q0g + r;
        uint4 v = make_uint4(0,0,0,0);
        if (qg < Ss) {
            const __nv_bfloat16* src = (p ? Ql_ : Qh_) + (size_t)(b*Ss + qg)*Dd + h*64 + ch*8;
            v = *(const uint4*)src;
        }
        *(uint4*)(sm + (p ? S1_OQL : S1_OQH) + r*144 + ch*16) = v;
    }
    // K planes: 2 x 208 rows x 8 chunks
    for (int t = tid; t < 3328; t += 256) {
        int p = t / 1664, rem = t % 1664;
        int kk = rem >> 3, ch = rem & 7;
        uint4 v = make_uint4(0,0,0,0);
        if (kk < NSP) {
            const __nv_bfloat16* src = (p ? Kl_ : Kh_) + (size_t)(b*Ss + f*NSP + kk)*Dd + h*64 + ch*8;
            v = *(const uint4*)src;
        }
        *(uint4*)(sm + (p ? S1_OKL : S1_OKH) + kk*144 + ch*16) = v;
    }
    // V planes: 2 x 208 rows x 8 chunks
    for (int t = tid; t < 3328; t += 256) {
        int p = t / 1664, rem = t % 1664;
        int kk = rem >> 3, ch = rem & 7;
        uint4 v = make_uint4(0,0,0,0);
        if (kk < NSP) {
            const __nv_bfloat16* src = (p ? Vl_ : Vh_) + (size_t)(b*Ss + f*NSP + kk)*Dd + h*64 + ch*8;
            v = *(const uint4*)src;
        }
        *(uint4*)(sm + (p ? S1_OVL : S1_OVH) + kk*144 + ch*16) = v;
    }
    __syncthreads();

    const int ra = (lane & 7) + ((lane >> 3) & 1) * 8;
    const int ca = (lane >> 4) & 1;
    const int rb = (lane & 7) + ((lane >> 4) & 1) * 8;
    const int cb = (lane >> 3) & 1;

    float c[2][13][4];
#pragma unroll
    for (int i = 0; i < 2; i++)
#pragma unroll
        for (int j = 0; j < 13; j++)
#pragma unroll
            for (int e = 0; e < 4; e++) c[i][j][e] = 0.f;

    {
        uint32_t aQh = sb + S1_OQH + (wm*32 + ra)*144 + ca*16;
        uint32_t aQl = sb + S1_OQL + (wm*32 + ra)*144 + ca*16;
        uint32_t aKh = sb + S1_OKH + (wn*104 + rb)*144 + cb*16;
        uint32_t aKl = sb + S1_OKL + (wn*104 + rb)*144 + cb*16;
#pragma unroll
        for (int ks = 0; ks < 4; ks++) {
            uint32_t ah[2][4], al[2][4], bh_[7][4], bl_[7][4];
            ldmx4(ah[0], aQh + ks*32);
            ldmx4(ah[1], aQh + 16*144 + ks*32);
            ldmx4(al[0], aQl + ks*32);
            ldmx4(al[1], aQl + 16*144 + ks*32);
#pragma unroll
            for (int j = 0; j < 7; j++) {
                ldmx4(bh_[j], aKh + j*16*144 + ks*32);
                ldmx4(bl_[j], aKl + j*16*144 + ks*32);
            }
#pragma unroll
            for (int mi = 0; mi < 2; mi++)
#pragma unroll
                for (int nj = 0; nj < 13; nj++) {
                    const uint32_t* bhp = &bh_[nj >> 1][(nj & 1) * 2];
                    const uint32_t* blp = &bl_[nj >> 1][(nj & 1) * 2];
                    mma_bf16(c[mi][nj], ah[mi], bhp);
                    mma_bf16(c[mi][nj], al[mi], bhp);
                    mma_bf16(c[mi][nj], ah[mi], blp);
                }
        }
    }

    float* rmax = (float*)(sm + S1_ORMAX);
    float* rsum = (float*)(sm + S1_ORSUM);
    const int qr = lane >> 2, qc = (lane & 3) * 2;

    float mx[2][2] = {{-1e30f,-1e30f},{-1e30f,-1e30f}};
#pragma unroll
    for (int mi = 0; mi < 2; mi++)
#pragma unroll
        for (int nj = 0; nj < 13; nj++) {
            int col = wn*104 + nj*8 + qc;
            if (col < NSP) {
#pragma unroll
                for (int hf = 0; hf < 2; hf++)
                    mx[mi][hf] = fmaxf(mx[mi][hf], fmaxf(c[mi][nj][hf*2], c[mi][nj][hf*2+1]));
            }
        }
#pragma unroll
    for (int mi = 0; mi < 2; mi++)
#pragma unroll
        for (int hf = 0; hf < 2; hf++) {
            float m = mx[mi][hf];
            m = fmaxf(m, __shfl_xor_sync(0xffffffffu, m, 1));
            m = fmaxf(m, __shfl_xor_sync(0xffffffffu, m, 2));
            if ((lane & 3) == 0)
                rmax[wn*128 + wm*32 + mi*16 + qr + hf*8] = m;
        }
    __syncthreads();

    float Mv[2][2], sum_[2][2] = {{0,0},{0,0}};
#pragma unroll
    for (int mi = 0; mi < 2; mi++)
#pragma unroll
        for (int hf = 0; hf < 2; hf++) {
            int row = wm*32 + mi*16 + qr + hf*8;
            Mv[mi][hf] = fmaxf(rmax[row], rmax[128 + row]);
        }
#pragma unroll
    for (int mi = 0; mi < 2; mi++)
#pragma unroll
        for (int nj = 0; nj < 13; nj++) {
            int col = wn*104 + nj*8 + qc;
            bool valid = col < NSP;
#pragma unroll
            for (int hf = 0; hf < 2; hf++) {
                float e0 = valid ? __expf(SCALE*(c[mi][nj][hf*2]   - Mv[mi][hf])) : 0.f;
                float e1 = valid ? __expf(SCALE*(c[mi][nj][hf*2+1] - Mv[mi][hf])) : 0.f;
                c[mi][nj][hf*2]   = e0;
                c[mi][nj][hf*2+1] = e1;
                sum_[mi][hf] += e0 + e1;
            }
        }
#pragma unroll
    for (int mi = 0; mi < 2; mi++)
#pragma unroll
        for (int hf = 0; hf < 2; hf++) {
            float s = sum_[mi][hf];
            s += __shfl_xor_sync(0xffffffffu, s, 1);
            s += __shfl_xor_sync(0xffffffffu, s, 2);
            if ((lane & 3) == 0)
                rsum[wn*128 + wm*32 + mi*16 + qr + hf*8] = s;
        }
    __syncthreads();

#pragma unroll
    for (int mi = 0; mi < 2; mi++)
#pragma unroll
        for (int hf = 0; hf < 2; hf++) {
            int row = wm*32 + mi*16 + qr + hf*8;
            int qg  = q0g + row;
            float inv = 1.f / (rsum[row] + rsum[128 + row]);
            bool rowv = qg < Ss;
            float* sap = rowv ? &SA[((size_t)(bh*Ss + qg)*Ff + f)*NSP] : nullptr;
#pragma unroll
            for (int nj = 0; nj < 13; nj++) {
                int col = wn*104 + nj*8 + qc;
                float p0 = c[mi][nj][hf*2]   * inv;
                float p1 = c[mi][nj][hf*2+1] * inv;
                if (rowv && col < NSP)
                    *(float2*)&sap[col] = make_float2(p0, p1);
                uint32_t hb, lb;
                split2(p0, p1, hb, lb);
                *(uint32_t*)(sm + S1_OPH + row*464 + col*2) = hb;
                *(uint32_t*)(sm + S1_OPL + row*464 + col*2) = lb;
            }
        }
    __syncthreads();

    float c2[2][4][4];
#pragma unroll
    for (int i = 0; i < 2; i++)
#pragma unroll
        for (int j = 0; j < 4; j++)
#pragma unroll
            for (int e = 0; e < 4; e++) c2[i][j][e] = 0.f;

    {
        const int rv = (lane & 7) + ((lane >> 3) & 1) * 8;
        const int cv = (lane >> 4) & 1;
        uint32_t aPh = sb + S1_OPH + (wm*32 + ra)*464 + ca*16;
        uint32_t aPl = sb + S1_OPL + (wm*32 + ra)*464 + ca*16;
        uint32_t aVh = sb + S1_OVH + rv*144 + (wn*32)*2 + cv*16;
        uint32_t aVl = sb + S1_OVL + rv*144 + (wn*32)*2 + cv*16;
#pragma unroll
        for (int ks = 0; ks < 13; ks++) {
            uint32_t ph[2][4], pl[2][4], vh[2][4], vl[2][4];
            ldmx4(ph[0], aPh + ks*32);
            ldmx4(ph[1], aPh + 16*464 + ks*32);
            ldmx4(pl[0], aPl + ks*32);
            ldmx4(pl[1], aPl + 16*464 + ks*32);
            ldmx4t(vh[0], aVh + ks*16*144);
            ldmx4t(vh[1], aVh + ks*16*144 + 32);
            ldmx4t(vl[0], aVl + ks*16*144);
            ldmx4t(vl[1], aVl + ks*16*144 + 32);
#pragma unroll
            for (int mi = 0; mi < 2; mi++)
#pragma unroll
                for (int nj = 0; nj < 4; nj++) {
                    const uint32_t* bhp = &vh[nj >> 1][(nj & 1) * 2];
                    const uint32_t* blp = &vl[nj >> 1][(nj & 1) * 2];
                    mma_bf16(c2[mi][nj], ph[mi], bhp);
                    mma_bf16(c2[mi][nj], pl[mi], bhp);
                    mma_bf16(c2[mi][nj], ph[mi], blp);
                }
        }
    }

#pragma unroll
    for (int mi = 0; mi < 2; mi++)
#pragma unroll
        for (int hf = 0; hf < 2; hf++) {
            int row = wm*32 + mi*16 + qr + hf*8;
            int qg  = q0g + row;
            if (qg >= Ss) continue;
            size_t base = ((size_t)(b*Ss + qg)*Ff + f)*Dd + h*64;
#pragma unroll
            for (int nj = 0; nj < 4; nj++) {
                int col = wn*32 + nj*8 + qc;
                uint32_t hb, lb;
                split2(c2[mi][nj][hf*2], c2[mi][nj][hf*2+1], hb, lb);
                *(uint32_t*)&XH[base + col] = hb;
                *(uint32_t*)&XL[base + col] = lb;
            }
        }
}

// ============================================================
// Diagonal gather on bf16 planes
// ============================================================
__global__ void diag_kernel(const uint2* __restrict__ XH, const uint2* __restrict__ XL,
                            uint2* __restrict__ XDH, uint2* __restrict__ XDL)
{
    int idx = blockIdx.x * blockDim.x + threadIdx.x;
    if (idx >= BSD/4) return;
    int c4   = idx % (Dd/4);
    int rest = idx / (Dd/4);
    int s = rest % Ss;
    int b = rest / Ss;
    int f = s / NSP;
    size_t src = ((size_t)(b*Ss + s)*Ff + f)*(Dd/4) + c4;
    XDH[idx] = XH[src];
    XDL[idx] = XL[src];
}

// ============================================================
// traj: per token — logits from x·m + q2·bk2, softmax over F,
// xw[h] = sum_f attn*x_f -> bf16 planes
// ============================================================
__global__ __launch_bounds__(128) void traj_kernel(
    const __nv_bfloat16* __restrict__ xh, const __nv_bfloat16* __restrict__ xl,
    const __nv_bfloat16* __restrict__ q2h, const __nv_bfloat16* __restrict__ q2l,
    const float* __restrict__ M_, const float* __restrict__ bpkv,
    __nv_bfloat16* __restrict__ xwh, __nv_bfloat16* __restrict__ xwl)
{
    __shared__ float xs[Ff][768];
    __shared__ float bq[Hh];
    const int t = blockIdx.x;
    const int tid = threadIdx.x;
    const int wid = tid >> 5, lane = tid & 31;

    {
        const uint4* ph = (const uint4*)(xh + (size_t)t*Ff*768);
        const uint4* pl = (const uint4*)(xl + (size_t)t*Ff*768);
        for (int i = tid; i < 768; i += 128) {
            uint4 vh = ph[i], vl = pl[i];
            int f = (i * 8) / 768, j = (i * 8) % 768;
            const uint32_t* wh = (const uint32_t*)&vh;
            const uint32_t* wl = (const uint32_t*)&vl;
#pragma unroll
            for (int w = 0; w < 4; w++) {
                float2 fh = __bfloat1622float2(*(const __nv_bfloat162*)&wh[w]);
                float2 fl = __bfloat1622float2(*(const __nv_bfloat162*)&wl[w]);
                xs[f][j + w*2 + 0] = fh.x + fl.x;
                xs[f][j + w*2 + 1] = fh.y + fl.y;
            }
        }
    }
#pragma unroll
    for (int hh = 0; hh < 3; hh++) {
        int h = wid * 3 + hh;
        int d0 = h*64 + lane;
        float qa = __bfloat162float(q2h[(size_t)t*768 + d0])      + __bfloat162float(q2l[(size_t)t*768 + d0]);
        float qb = __bfloat162float(q2h[(size_t)t*768 + d0 + 32]) + __bfloat162float(q2l[(size_t)t*768 + d0 + 32]);
        float acc = qa * bpkv[d0] + qb * bpkv[d0 + 32];
#pragma unroll
        for (int o = 16; o > 0; o >>= 1) acc += __shfl_xor_sync(0xffffffffu, acc, o);
        if (lane == 0) bq[h] = acc;
    }
    __syncthreads();

#pragma unroll
    for (int hh = 0; hh < 3; hh++) {
        int h = wid * 3 + hh;
        const float* mh = M_ + (size_t)t*(Hh*768) + (size_t)h*768;
        float acc[Ff];
#pragma unroll
        for (int f = 0; f < Ff; f++) acc[f] = 0.f;
        for (int js = 0; js < 24; js++) {
            int j = js*32 + lane;
            float mv = mh[j];
#pragma unroll
            for (int f = 0; f < Ff; f++) acc[f] += xs[f][j] * mv;
        }
        float lg[Ff];
#pragma unroll
        for (int f = 0; f < Ff; f++) {
            float s = acc[f];
#pragma unroll
            for (int o = 16; o > 0; o >>= 1) s += __shfl_xor_sync(0xffffffffu, s, o);
            lg[f] = SCALE * (s + bq[h]);
        }
        float mm = lg[0];
#pragma unroll
        for (int f = 1; f < Ff; f++) mm = fmaxf(mm, lg[f]);
        float attn[Ff], sum = 0.f;
#pragma unroll
        for (int f = 0; f < Ff; f++) { attn[f] = __expf(lg[f] - mm); sum += attn[f]; }
        float inv = 1.f / sum;
#pragma unroll
        for (int f = 0; f < Ff; f++) attn[f] *= inv;

        size_t base = (size_t)t*(Hh*768) + (size_t)h*768;
        for (int i = 0; i < 12; i++) {
            int j0 = i*64 + lane*2;
            float a0 = 0.f, a1 = 0.f;
#pragma unroll
            for (int f = 0; f < Ff; f++) {
                a0 += attn[f] * xs[f][j0];
                a1 += attn[f] * xs[f][j0 + 1];
            }
            uint32_t hb, lb;
            split2(a0, a1, hb, lb);
            *(uint32_t*)&xwh[base + j0] = hb;
            *(uint32_t*)&xwl[base + j0] = lb;
        }
    }
}

// ============================================================
// launch
// ============================================================
extern "C" void kernel_launch(void* const* d_in, const int* in_sizes, int n_in,
                              void* d_out, int out_size)
{
    const float* query = (const float*)d_in[0];
    const float* key_t = (const float*)d_in[1];
    const float* value = (const float*)d_in[2];
    const float* Wq   = (const float*)d_in[3];
    const float* bq   = (const float*)d_in[4];
    const float* Wk   = (const float*)d_in[5];
    const float* bk   = (const float*)d_in[6];
    const float* Wv   = (const float*)d_in[7];
    const float* bv   = (const float*)d_in[8];
    const float* Wpq  = (const float*)d_in[9];
    const float* bpq  = (const float*)d_in[10];
    const float* Wpkv = (const float*)d_in[11];
    const float* bpkv = (const float*)d_in[12];
    const float* Wp   = (const float*)d_in[13];
    const float* bp   = (const float*)d_in[14];

    float* out = (float*)d_out;            // (B, S, D)
    float* sa  = out + BSD;                // (B*H, S, F, n)

    float *mbuf, *zerob, *bqkv;
    __nv_bfloat16 *wth, *wtl, *wk2h, *wk2l;
    __nv_bfloat16 *inh, *inl, *qkvh, *qkvl;
    __nv_bfloat16 *xh, *xl, *xdh, *xdl, *q2h, *q2l, *xwh, *xwl, *t2h, *t2l;
    cudaGetSymbolAddress((void**)&mbuf, g_m);
    cudaGetSymbolAddress((void**)&zerob, g_zerob);
    cudaGetSymbolAddress((void**)&bqkv, g_bqkv);
    cudaGetSymbolAddress((void**)&wth, g_wth);
    cudaGetSymbolAddress((void**)&wtl, g_wtl);
    cudaGetSymbolAddress((void**)&wk2h, g_wk2h);
    cudaGetSymbolAddress((void**)&wk2l, g_wk2l);
    cudaGetSymbolAddress((void**)&inh, g_inh);
    cudaGetSymbolAddress((void**)&inl, g_inl);
    cudaGetSymbolAddress((void**)&qkvh, g_qkvh);
    cudaGetSymbolAddress((void**)&qkvl, g_qkvl);
    cudaGetSymbolAddress((void**)&xh,  g_xh);
    cudaGetSymbolAddress((void**)&xl,  g_xl);
    cudaGetSymbolAddress((void**)&xdh, g_xdh);
    cudaGetSymbolAddress((void**)&xdl, g_xdl);
    cudaGetSymbolAddress((void**)&q2h, g_q2h);
    cudaGetSymbolAddress((void**)&q2l, g_q2l);
    cudaGetSymbolAddress((void**)&xwh, g_xwh);
    cudaGetSymbolAddress((void**)&xwl, g_xwl);
    cudaGetSymbolAddress((void**)&t2h, g_t2h);
    cudaGetSymbolAddress((void**)&t2l, g_t2l);

    cudaFuncSetAttribute(stage1_mma_kernel,
                         cudaFuncAttributeMaxDynamicSharedMemorySize, S1_SMEM);
    cudaFuncSetAttribute(gemm_tpl<0,128>,
                         cudaFuncAttributeMaxDynamicSharedMemorySize, SMEM_128);
    cudaFuncSetAttribute(gemm_tpl<1,128>,
                         cudaFuncAttributeMaxDynamicSharedMemorySize, SMEM_128);
    cudaFuncSetAttribute(gemm_tpl<1,64>,
                         cudaFuncAttributeMaxDynamicSharedMemorySize, SMEM_64);
    cudaFuncSetAttribute(gemm_tpl<0,64>,
                         cudaFuncAttributeMaxDynamicSharedMemorySize, SMEM_64);

    int n4 = BSD/4, sg = (n4 + 255)/256;
    dim3 wb(32, 8);

    // launch 0: merged wtrans for Wq|Wk|Wv
    wtrans3_kernel<<<dim3(24,24,3), wb>>>(Wq, Wk, Wv, wth, wtl);
    // launch 1: merged input split
    split3_kernel<<<dim3(sg,3), 256>>>((const float4*)query, (const float4*)key_t,
                                       (const float4*)value, (uint2*)inh, (uint2*)inl, n4);
    // launch 2: bias pack
    biaspack_kernel<<<9, 256>>>(bq, bk, bv, bqkv);

    // launch 3 (ncu capture target): merged q/k/v projection, grid z=3
    gemm_tpl<1,128><<<dim3(6,25,3), 256, SMEM_128>>>(
        inh, inl, 768, (long)BSD,
        wth+OFF_WQ, wtl+OFF_WQ, 768, (long)WSQ,
        bqkv, 768,
        nullptr, qkvh, qkvl, 768, (long)BSD,
        BS, 768);

    // remaining weight prep
    wtrans_kernel<<<dim3(24,24), wb>>>(Wpq, wth+OFF_WPQ, wtl+OFF_WPQ, 768, 768);
    wtrans_kernel<<<dim3(24,24), wb>>>(Wp,  wth+OFF_WP,  wtl+OFF_WP,  768, 768);
    wtrans_kernel<<<dim3(48,24), wb>>>(Wpkv, wth+OFF_WPKV, wtl+OFF_WPKV, 768, 1536);
    splitwk2_kernel<<<(768*192 + 255)/256, 256>>>(Wpkv, wk2h, wk2l);

    stage1_mma_kernel<<<dim3(13, Ff, Bb*Hh), 256, S1_SMEM>>>(
        qkvh, qkvl, qkvh + BSD, qkvl + BSD, qkvh + 2*BSD, qkvl + 2*BSD, xh, xl, sa);

    diag_kernel<<<(BSD/4 + 255)/256, 256>>>(
        (const uint2*)xh, (const uint2*)xl, (uint2*)xdh, (uint2*)xdl);

    // q2 = xd @ Wpq + bpq  (split output), NTILE=64 -> 300 CTAs
    gemm_tpl<1,64><<<dim3(12, 25, 1), 256, SMEM_64>>>(
        xdh, xdl, 768, 0, wth+OFF_WPQ, wtl+OFF_WPQ, 768, 0,
        bpq, 0, nullptr, q2h, q2l, 768, 0, BS, 768);

    // m[t,h,:] = Wk2[:,hslice] @ q2_h : per-head GEMM M=BS, N=768, K=64
    gemm_tpl<0,128><<<dim3(6, 25, 12), 256, SMEM_128>>>(
        q2h, q2l, 768, 64,
        wk2h, wk2l, 768, 64,
        zerob, 0,
        mbuf, nullptr, nullptr, Hh*768, 768,
        BS, 64);

    // logits + softmax + xw
    traj_kernel<<<BS, 128>>>(xh, xl, q2h, q2l, mbuf, bpkv, xwh, xwl);

    // o_h = xw_h @ Wv2[:,hslice] + bv2_h : per-head GEMM M=BS, N=64, K=768 -> t2 planes
    gemm_tpl<1,64><<<dim3(1, 25, 12), 256, SMEM_64>>>(
        xwh, xwl, Hh*768, 768,
        wth + OFF_WPKV + (size_t)768*768, wtl + OFF_WPKV + (size_t)768*768, 768, (long)64*768,
        bpkv + 768, 64,
        nullptr, t2h, t2l, 768, 64,
        BS, 768);

    // out = t2 @ Wp + bp, NTILE=64 -> 300 CTAs
    gemm_tpl<0,64><<<dim3(12, 25, 1), 256, SMEM_64>>>(
        t2h, t2l, 768, 0, wth+OFF_WP, wtl+OFF_WP, 768, 0,
        bp, 0, out, nullptr, nullptr, 768, 0, BS, 768);
}

// round 14
// speedup vs baseline: 1.0585x; 1.0211x over previous
#include <cuda_runtime.h>
#include <cuda_bf16.h>
#include <cstdint>
#include <cstddef>

// ---- problem constants ----
#define Bb   2
#define Ss   1568
#define Dd   768
#define Hh   12
#define HDd  64
#define Ff   8
#define NSP  196
#define BS   (Bb*Ss)             // 3136
#define BSD  (Bb*Ss*Dd)          // 2408448
#define XSZ  (Bb*Ss*Ff*Dd)       // 19267584
#define SCALE 0.125f

// ---- scratch ----
__device__ float g_m[(size_t)BS*Hh*Dd];      // [t][h][768] fp32 logit-matrices
__device__ float g_zerob[768];               // zero bias (static-zeroed)
__device__ float g_bqkv[3*768];              // packed bq|bk|bv

// bf16 hi/lo planes (contiguous for batched GEMMs)
__device__ __align__(16) __nv_bfloat16 g_inh[3*BSD], g_inl[3*BSD];     // query|key|value split
__device__ __align__(16) __nv_bfloat16 g_qkvh[3*BSD], g_qkvl[3*BSD];   // projected q|k|v
__device__ __align__(16) __nv_bfloat16 g_xh [XSZ], g_xl [XSZ];
__device__ __align__(16) __nv_bfloat16 g_xdh[BSD], g_xdl[BSD];
__device__ __align__(16) __nv_bfloat16 g_q2h[BSD], g_q2l[BSD];
__device__ __align__(16) __nv_bfloat16 g_xwh[(size_t)BS*Hh*Dd], g_xwl[(size_t)BS*Hh*Dd];
__device__ __align__(16) __nv_bfloat16 g_t2h[BSD], g_t2l[BSD];
__device__ __align__(16) __nv_bfloat16 g_wk2h[768*768], g_wk2l[768*768]; // Wpkv[:, :768] row-major split

// transposed+split weights: [N][K] bf16, hi and lo parts
#define WSQ  (768*768)
#define OFF_WQ   0
#define OFF_WK   (1*WSQ)
#define OFF_WV   (2*WSQ)
#define OFF_WPQ  (3*WSQ)
#define OFF_WP   (4*WSQ)
#define OFF_WPKV (5*WSQ)
#define WT_ELEMS (5*WSQ + 1536*768)
__device__ __align__(16) __nv_bfloat16 g_wth[WT_ELEMS];
__device__ __align__(16) __nv_bfloat16 g_wtl[WT_ELEMS];

// ============================================================
// helpers
// ============================================================
__device__ __forceinline__ uint32_t smem_u32(const void* p) {
    uint32_t a;
    asm("{ .reg .u64 t; cvta.to.shared.u64 t, %1; cvt.u32.u64 %0, t; }" : "=r"(a) : "l"(p));
    return a;
}
__device__ __forceinline__ void ldmx4(uint32_t* r, uint32_t a) {
    asm volatile("ldmatrix.sync.aligned.m8n8.x4.shared.b16 {%0,%1,%2,%3}, [%4];"
        : "=r"(r[0]), "=r"(r[1]), "=r"(r[2]), "=r"(r[3]) : "r"(a));
}
__device__ __forceinline__ void ldmx4t(uint32_t* r, uint32_t a) {
    asm volatile("ldmatrix.sync.aligned.m8n8.x4.trans.shared.b16 {%0,%1,%2,%3}, [%4];"
        : "=r"(r[0]), "=r"(r[1]), "=r"(r[2]), "=r"(r[3]) : "r"(a));
}
__device__ __forceinline__ void mma_bf16(float* c, const uint32_t* a, const uint32_t* b) {
    asm volatile("mma.sync.aligned.m16n8k16.row.col.f32.bf16.bf16.f32 "
        "{%0,%1,%2,%3}, {%4,%5,%6,%7}, {%8,%9}, {%0,%1,%2,%3};"
        : "+f"(c[0]), "+f"(c[1]), "+f"(c[2]), "+f"(c[3])
        : "r"(a[0]), "r"(a[1]), "r"(a[2]), "r"(a[3]), "r"(b[0]), "r"(b[1]));
}
#define CP_ASYNC16(dst, src, sz) \
    asm volatile("cp.async.cg.shared.global [%0], [%1], 16, %2;" \
                 :: "r"(dst), "l"(src), "r"(sz))
#define CP_COMMIT() asm volatile("cp.async.commit_group;" ::: "memory")
#define CP_WAIT(n)  asm volatile("cp.async.wait_group %0;" :: "n"(n) : "memory")

__device__ __forceinline__ void split2(float a, float b, uint32_t& h, uint32_t& l) {
    __nv_bfloat162 hh = __floats2bfloat162_rn(a, b);
    float2 f = __bfloat1622float2(hh);
    __nv_bfloat162 ll = __floats2bfloat162_rn(a - f.x, b - f.y);
    h = *(uint32_t*)&hh; l = *(uint32_t*)&ll;
}

// ============================================================
// merged weight transpose+split for Wq|Wk|Wv via grid.z
// ============================================================
__global__ void wtrans3_kernel(const float* __restrict__ W0, const float* __restrict__ W1,
                               const float* __restrict__ W2,
                               __nv_bfloat16* __restrict__ hi, __nv_bfloat16* __restrict__ lo)
{
    __shared__ float t[32][33];
    const float* W = blockIdx.z == 0 ? W0 : (blockIdx.z == 1 ? W1 : W2);
    size_t wo = (size_t)blockIdx.z * WSQ;
    int n0 = blockIdx.x * 32, k0 = blockIdx.y * 32;
    int tx = threadIdx.x, ty = threadIdx.y;
#pragma unroll
    for (int i = 0; i < 32; i += 8)
        t[ty + i][tx] = W[(size_t)(k0 + ty + i) * 768 + n0 + tx];
    __syncthreads();
#pragma unroll
    for (int i = 0; i < 32; i += 8) {
        float v = t[tx][ty + i];
        __nv_bfloat16 h = __float2bfloat16(v);
        __nv_bfloat16 l = __float2bfloat16(v - __bfloat162float(h));
        size_t o = wo + (size_t)(n0 + ty + i) * 768 + k0 + tx;
        hi[o] = h; lo[o] = l;
    }
}

__global__ void wtrans_kernel(const float* __restrict__ W,
                              __nv_bfloat16* __restrict__ hi,
                              __nv_bfloat16* __restrict__ lo, int K, int N)
{
    __shared__ float t[32][33];
    int n0 = blockIdx.x * 32, k0 = blockIdx.y * 32;
    int tx = threadIdx.x, ty = threadIdx.y;
#pragma unroll
    for (int i = 0; i < 32; i += 8)
        t[ty + i][tx] = W[(size_t)(k0 + ty + i) * N + n0 + tx];
    __syncthreads();
#pragma unroll
    for (int i = 0; i < 32; i += 8) {
        float v = t[tx][ty + i];
        __nv_bfloat16 h = __float2bfloat16(v);
        __nv_bfloat16 l = __float2bfloat16(v - __bfloat162float(h));
        size_t o = (size_t)(n0 + ty + i) * K + k0 + tx;
        hi[o] = h; lo[o] = l;
    }
}

// ============================================================
// merged elementwise fp32 -> bf16 hi/lo planes (3 inputs via grid.y)
// ============================================================
__global__ void split3_kernel(const float4* __restrict__ a0, const float4* __restrict__ a1,
                              const float4* __restrict__ a2,
                              uint2* __restrict__ H, uint2* __restrict__ L, int n4)
{
    int i = blockIdx.x * blockDim.x + threadIdx.x;
    if (i >= n4) return;
    int which = blockIdx.y;
    const float4* in = which == 0 ? a0 : (which == 1 ? a1 : a2);
    float4 a = in[i];
    uint32_t h01, l01, h23, l23;
    split2(a.x, a.y, h01, l01);
    split2(a.z, a.w, h23, l23);
    size_t o = (size_t)which * n4 + i;
    H[o] = make_uint2(h01, h23);
    L[o] = make_uint2(l01, l23);
}

__global__ void biaspack_kernel(const float* __restrict__ b0, const float* __restrict__ b1,
                                const float* __restrict__ b2, float* __restrict__ dst)
{
    int i = blockIdx.x * blockDim.x + threadIdx.x;
    if (i >= 3*768) return;
    int w = i / 768, j = i % 768;
    dst[i] = (w == 0 ? b0 : (w == 1 ? b1 : b2))[j];
}

__global__ void splitwk2_kernel(const float* __restrict__ Wpkv,
                                __nv_bfloat16* __restrict__ H, __nv_bfloat16* __restrict__ L)
{
    int i = blockIdx.x * blockDim.x + threadIdx.x;
    if (i >= 768*192) return;
    int j = i / 192, c4 = (i % 192) * 4;
    float4 a = *(const float4*)&Wpkv[(size_t)j * 1536 + c4];
    uint32_t h01, l01, h23, l23;
    split2(a.x, a.y, h01, l01);
    split2(a.z, a.w, h23, l23);
    *(uint2*)&H[(size_t)j*768 + c4] = make_uint2(h01, h23);
    *(uint2*)&L[(size_t)j*768 + c4] = make_uint2(l01, l23);
}

// ============================================================
// HMMA bf16x3 GEMM, swizzled 64B-row smem (compact, conflict-free).
// Physical chunk = c ^ ((row>>1)&3). NTILE in {128, 64}.
// Stage: A 2x8192 + B 2x(NTILE*64). 128-tile: 32KB/stage -> 3 CTAs/SM.
// ============================================================
template <int OUT_SPLIT, int NTILE>
__device__ __forceinline__ void gemm_body(
    const __nv_bfloat16* __restrict__ Ah, const __nv_bfloat16* __restrict__ Al, int lda,
    const __nv_bfloat16* __restrict__ Bh, const __nv_bfloat16* __restrict__ Bl, int ldb,
    const float* __restrict__ bias,
    float* __restrict__ C, __nv_bfloat16* __restrict__ CH, __nv_bfloat16* __restrict__ CL,
    int ldc, int M, int K)
{
    constexpr int NJ   = NTILE / 16;
    constexpr int APL  = 8192;             // bytes per A plane (128 x 64)
    constexpr int BPL  = NTILE * 64;       // bytes per B plane
    constexpr int STG  = 2*APL + 2*BPL;    // bytes per stage
    constexpr int CPN  = 1024 + NTILE * 8;

    extern __shared__ char smem[];
    const uint32_t sb = smem_u32(smem);
    const int tid = threadIdx.x;
    const int wid = tid >> 5, lane = tid & 31;
    const int bm = blockIdx.y * 128, bn = blockIdx.x * NTILE;
    const int m0 = (wid & 3) * 32;
    const int n0 = (wid >> 2) * (NTILE / 2);

    float c[2][NJ][4];
#pragma unroll
    for (int i = 0; i < 2; i++)
#pragma unroll
        for (int j = 0; j < NJ; j++)
#pragma unroll
            for (int e = 0; e < 4; e++) c[i][j][e] = 0.f;

    const int ra = (lane & 7) + ((lane >> 3) & 1) * 8;
    const int ca = (lane >> 4) & 1;
    const int rb = (lane & 7) + ((lane >> 4) & 1) * 8;
    const int cb = (lane >> 3) & 1;
    const int swzA = (ra >> 1) & 3;        // m0,16-row steps preserve this
    const int swzB = (rb >> 1) & 3;        // n0,16-row steps preserve this

    auto issue = [&](int kb, int s) {
        for (int i = tid; i < CPN; i += 256) {
            uint32_t dst, sz = 16;
            const __nv_bfloat16* src;
            if (i < 1024) {
                int p = i >> 9, rem = i & 511;
                int row = rem >> 2, c4 = rem & 3;
                int pc = c4 ^ ((row >> 1) & 3);
                dst = sb + s * STG + p * APL + row * 64 + pc * 16;
                int gm = bm + row;
                int g  = gm < M ? gm : 0;
                if (gm >= M) sz = 0;
                src = (p == 0 ? Ah : Al) + (size_t)g * lda + kb + c4 * 8;
            } else {
                int i2 = i - 1024;
                int p = i2 / (NTILE * 4), rem = i2 % (NTILE * 4);
                int row = rem >> 2, c4 = rem & 3;
                int pc = c4 ^ ((row >> 1) & 3);
                dst = sb + s * STG + 2*APL + p * BPL + row * 64 + pc * 16;
                src = (p == 0 ? Bh : Bl) + (size_t)(bn + row) * ldb + kb + c4 * 8;
            }
            CP_ASYNC16(dst, src, sz);
        }
    };

    issue(0, 0);
    CP_COMMIT();

    int s = 0;
    for (int kb = 0; kb < K; kb += 32, s ^= 1) {
        if (kb + 32 < K) {
            issue(kb + 32, s ^ 1);
            CP_COMMIT();
            CP_WAIT(1);
        } else {
            CP_WAIT(0);
        }
        __syncthreads();

        uint32_t base = sb + s * STG;
        uint32_t rAh = base +       (m0 + ra) * 64;
        uint32_t rAl = base + APL + (m0 + ra) * 64;
        uint32_t rBh = base + 2*APL +       (n0 + rb) * 64;
        uint32_t rBl = base + 2*APL + BPL + (n0 + rb) * 64;

#pragma unroll
        for (int ks = 0; ks < 2; ks++) {
            const uint32_t choA = (uint32_t)(((ks*2 + ca) ^ swzA) * 16);
            const uint32_t choB = (uint32_t)(((ks*2 + cb) ^ swzB) * 16);
            uint32_t ah[2][4], al[2][4], bh[NJ/2][4], bl[NJ/2][4];
            ldmx4(ah[0], rAh + choA);
            ldmx4(ah[1], rAh + 1024 + choA);
            ldmx4(al[0], rAl + choA);
            ldmx4(al[1], rAl + 1024 + choA);
#pragma unroll
            for (int j = 0; j < NJ/2; j++) {
                ldmx4(bh[j], rBh + j * 1024 + choB);
                ldmx4(bl[j], rBl + j * 1024 + choB);
            }
#pragma unroll
            for (int mi = 0; mi < 2; mi++)
#pragma unroll
                for (int nj = 0; nj < NJ; nj++) {
                    const uint32_t* bhp = &bh[nj >> 1][(nj & 1) * 2];
                    const uint32_t* blp = &bl[nj >> 1][(nj & 1) * 2];
                    mma_bf16(c[mi][nj], ah[mi], bhp);
                    mma_bf16(c[mi][nj], al[mi], bhp);
                    mma_bf16(c[mi][nj], ah[mi], blp);
                }
        }
        __syncthreads();
    }

    const int cr = lane >> 2, cc = (lane & 3) * 2;
#pragma unroll
    for (int nj = 0; nj < NJ; nj++) {
        int bcol = bn + n0 + nj * 8 + cc;
        float b0 = bias[bcol], b1 = bias[bcol + 1];
#pragma unroll
        for (int mi = 0; mi < 2; mi++) {
#pragma unroll
            for (int hf = 0; hf < 2; hf++) {
                int r = bm + m0 + mi * 16 + cr + hf * 8;
                if (r >= M) continue;
                float o0 = c[mi][nj][hf*2+0] + b0;
                float o1 = c[mi][nj][hf*2+1] + b1;
                if (OUT_SPLIT) {
                    uint32_t h, l;
                    split2(o0, o1, h, l);
                    *(uint32_t*)&CH[(size_t)r * ldc + bcol] = h;
                    *(uint32_t*)&CL[(size_t)r * ldc + bcol] = l;
                } else {
                    *(float2*)&C[(size_t)r * ldc + bcol] = make_float2(o0, o1);
                }
            }
        }
    }
}

template <int OUT_SPLIT, int NTILE>
__global__ __launch_bounds__(256) void gemm_tpl(
    const __nv_bfloat16* Ah, const __nv_bfloat16* Al, int lda, long aZ,
    const __nv_bfloat16* Bh, const __nv_bfloat16* Bl, int ldb, long bZ,
    const float* bias, long biasZ,
    float* C, __nv_bfloat16* CH, __nv_bfloat16* CL, int ldc, long cZ,
    int M, int K)
{
    long z = blockIdx.z;
    gemm_body<OUT_SPLIT, NTILE>(
        Ah + z*aZ, Al + z*aZ, lda,
        Bh + z*bZ, Bl + z*bZ, ldb,
        bias + z*biasZ,
        C  ? C  + z*cZ : nullptr,
        CH ? CH + z*cZ : nullptr,
        CL ? CL + z*cZ : nullptr,
        ldc, M, K);
}

#define SMEM_128 65536
#define SMEM_64  49152

// ============================================================
// Stage 1 (HMMA): per (b,h,f, 128-query tile) fused attention.
// K/V: 208 rows loaded (196 real + 12 zero); P cols 0..207; PV 13 ksteps.
// ============================================================
#define S1_OPH   0
#define S1_OPL   59392
#define S1_OQH   0
#define S1_OQL   18432
#define S1_OKH   36864
#define S1_OKL   69120
#define S1_OVH   118784
#define S1_OVL   151040
#define S1_ORMAX 183296
#define S1_ORSUM 184320
#define S1_SMEM  185344

__global__ __launch_bounds__(256) void stage1_mma_kernel(
    const __nv_bfloat16* __restrict__ Qh_, const __nv_bfloat16* __restrict__ Ql_,
    const __nv_bfloat16* __restrict__ Kh_, const __nv_bfloat16* __restrict__ Kl_,
    const __nv_bfloat16* __restrict__ Vh_, const __nv_bfloat16* __restrict__ Vl_,
    __nv_bfloat16* __restrict__ XH, __nv_bfloat16* __restrict__ XL,
    float* __restrict__ SA)
{
    extern __shared__ char sm[];
    const uint32_t sb = smem_u32(sm);
    const int tid = threadIdx.x;
    const int wid = tid >> 5, lane = tid & 31;
    const int wm = wid & 3, wn = wid >> 2;
    const int q0g = blockIdx.x * 128;
    const int f   = blockIdx.y;
    const int bh  = blockIdx.z;
    const int b   = bh / Hh, h = bh % Hh;

    for (int t = tid; t < 2048; t += 256) {
        int p = t >> 10, r = (t >> 3) & 127, ch = t & 7;
        int qg = q0g + r;
        uint4 v = make_uint4(0,0,0,0);
        if (qg < Ss) {
            const __nv_bfloat16* src = (p ? Ql_ : Qh_) + (size_t)(b*Ss + qg)*Dd + h*64 + ch*8;
            v = *(const uint4*)src;
        }
        *(uint4*)(sm + (p ? S1_OQL : S1_OQH) + r*144 + ch*16) = v;
    }
    for (int t = tid; t < 3328; t += 256) {
        int p = t / 1664, rem = t % 1664;
        int kk = rem >> 3, ch = rem & 7;
        uint4 v = make_uint4(0,0,0,0);
        if (kk < NSP) {
            const __nv_bfloat16* src = (p ? Kl_ : Kh_) + (size_t)(b*Ss + f*NSP + kk)*Dd + h*64 + ch*8;
            v = *(const uint4*)src;
        }
        *(uint4*)(sm + (p ? S1_OKL : S1_OKH) + kk*144 + ch*16) = v;
    }
    for (int t = tid; t < 3328; t += 256) {
        int p = t / 1664, rem = t % 1664;
        int kk = rem >> 3, ch = rem & 7;
        uint4 v = make_uint4(0,0,0,0);
        if (kk < NSP) {
            const __nv_bfloat16* src = (p ? Vl_ : Vh_) + (size_t)(b*Ss + f*NSP + kk)*Dd + h*64 + ch*8;
            v = *(const uint4*)src;
        }
        *(uint4*)(sm + (p ? S1_OVL : S1_OVH) + kk*144 + ch*16) = v;
    }
    __syncthreads();

    const int ra = (lane & 7) + ((lane >> 3) & 1) * 8;
    const int ca = (lane >> 4) & 1;
    const int rb = (lane & 7) + ((lane >> 4) & 1) * 8;
    const int cb = (lane >> 3) & 1;

    float c[2][13][4];
#pragma unroll
    for (int i = 0; i < 2; i++)
#pragma unroll
        for (int j = 0; j < 13; j++)
#pragma unroll
            for (int e = 0; e < 4; e++) c[i][j][e] = 0.f;

    {
        uint32_t aQh = sb + S1_OQH + (wm*32 + ra)*144 + ca*16;
        uint32_t aQl = sb + S1_OQL + (wm*32 + ra)*144 + ca*16;
        uint32_t aKh = sb + S1_OKH + (wn*104 + rb)*144 + cb*16;
        uint32_t aKl = sb + S1_OKL + (wn*104 + rb)*144 + cb*16;
#pragma unroll
        for (int ks = 0; ks < 4; ks++) {
            uint32_t ah[2][4], al[2][4], bh_[7][4], bl_[7][4];
            ldmx4(ah[0], aQh + ks*32);
            ldmx4(ah[1], aQh + 16*144 + ks*32);
            ldmx4(al[0], aQl + ks*32);
            ldmx4(al[1], aQl + 16*144 + ks*32);
#pragma unroll
            for (int j = 0; j < 7; j++) {
                ldmx4(bh_[j], aKh + j*16*144 + ks*32);
                ldmx4(bl_[j], aKl + j*16*144 + ks*32);
            }
#pragma unroll
            for (int mi = 0; mi < 2; mi++)
#pragma unroll
                for (int nj = 0; nj < 13; nj++) {
                    const uint32_t* bhp = &bh_[nj >> 1][(nj & 1) * 2];
                    const uint32_t* blp = &bl_[nj >> 1][(nj & 1) * 2];
                    mma_bf16(c[mi][nj], ah[mi], bhp);
                    mma_bf16(c[mi][nj], al[mi], bhp);
                    mma_bf16(c[mi][nj], ah[mi], blp);
                }
        }
    }

    float* rmax = (float*)(sm + S1_ORMAX);
    float* rsum = (float*)(sm + S1_ORSUM);
    const int qr = lane >> 2, qc = (lane & 3) * 2;

    float mx[2][2] = {{-1e30f,-1e30f},{-1e30f,-1e30f}};
#pragma unroll
    for (int mi = 0; mi < 2; mi++)
#pragma unroll
        for (int nj = 0; nj < 13; nj++) {
            int col = wn*104 + nj*8 + qc;
            if (col < NSP) {
#pragma unroll
                for (int hf = 0; hf < 2; hf++)
                    mx[mi][hf] = fmaxf(mx[mi][hf], fmaxf(c[mi][nj][hf*2], c[mi][nj][hf*2+1]));
            }
        }
#pragma unroll
    for (int mi = 0; mi < 2; mi++)
#pragma unroll
        for (int hf = 0; hf < 2; hf++) {
            float m = mx[mi][hf];
            m = fmaxf(m, __shfl_xor_sync(0xffffffffu, m, 1));
            m = fmaxf(m, __shfl_xor_sync(0xffffffffu, m, 2));
            if ((lane & 3) == 0)
                rmax[wn*128 + wm*32 + mi*16 + qr + hf*8] = m;
        }
    __syncthreads();

    float Mv[2][2], sum_[2][2] = {{0,0},{0,0}};
#pragma unroll
    for (int mi = 0; mi < 2; mi++)
#pragma unroll
        for (int hf = 0; hf < 2; hf++) {
            int row = wm*32 + mi*16 + qr + hf*8;
            Mv[mi][hf] = fmaxf(rmax[row], rmax[128 + row]);
        }
#pragma unroll
    for (int mi = 0; mi < 2; mi++)
#pragma unroll
        for (int nj = 0; nj < 13; nj++) {
            int col = wn*104 + nj*8 + qc;
            bool valid = col < NSP;
#pragma unroll
            for (int hf = 0; hf < 2; hf++) {
                float e0 = valid ? __expf(SCALE*(c[mi][nj][hf*2]   - Mv[mi][hf])) : 0.f;
                float e1 = valid ? __expf(SCALE*(c[mi][nj][hf*2+1] - Mv[mi][hf])) : 0.f;
                c[mi][nj][hf*2]   = e0;
                c[mi][nj][hf*2+1] = e1;
                sum_[mi][hf] += e0 + e1;
            }
        }
#pragma unroll
    for (int mi = 0; mi < 2; mi++)
#pragma unroll
        for (int hf = 0; hf < 2; hf++) {
            float s = sum_[mi][hf];
            s += __shfl_xor_sync(0xffffffffu, s, 1);
            s += __shfl_xor_sync(0xffffffffu, s, 2);
            if ((lane & 3) == 0)
                rsum[wn*128 + wm*32 + mi*16 + qr + hf*8] = s;
        }
    __syncthreads();

#pragma unroll
    for (int mi = 0; mi < 2; mi++)
#pragma unroll
        for (int hf = 0; hf < 2; hf++) {
            int row = wm*32 + mi*16 + qr + hf*8;
            int qg  = q0g + row;
            float inv = 1.f / (rsum[row] + rsum[128 + row]);
            bool rowv = qg < Ss;
            float* sap = rowv ? &SA[((size_t)(bh*Ss + qg)*Ff + f)*NSP] : nullptr;
#pragma unroll
            for (int nj = 0; nj < 13; nj++) {
                int col = wn*104 + nj*8 + qc;
                float p0 = c[mi][nj][hf*2]   * inv;
                float p1 = c[mi][nj][hf*2+1] * inv;
                if (rowv && col < NSP)
                    *(float2*)&sap[col] = make_float2(p0, p1);
                uint32_t hb, lb;
                split2(p0, p1, hb, lb);
                *(uint32_t*)(sm + S1_OPH + row*464 + col*2) = hb;
                *(uint32_t*)(sm + S1_OPL + row*464 + col*2) = lb;
            }
        }
    __syncthreads();

    float c2[2][4][4];
#pragma unroll
    for (int i = 0; i < 2; i++)
#pragma unroll
        for (int j = 0; j < 4; j++)
#pragma unroll
            for (int e = 0; e < 4; e++) c2[i][j][e] = 0.f;

    {
        const int rv = (lane & 7) + ((lane >> 3) & 1) * 8;
        const int cv = (lane >> 4) & 1;
        uint32_t aPh = sb + S1_OPH + (wm*32 + ra)*464 + ca*16;
        uint32_t aPl = sb + S1_OPL + (wm*32 + ra)*464 + ca*16;
        uint32_t aVh = sb + S1_OVH + rv*144 + (wn*32)*2 + cv*16;
        uint32_t aVl = sb + S1_OVL + rv*144 + (wn*32)*2 + cv*16;
#pragma unroll
        for (int ks = 0; ks < 13; ks++) {
            uint32_t ph[2][4], pl[2][4], vh[2][4], vl[2][4];
            ldmx4(ph[0], aPh + ks*32);
            ldmx4(ph[1], aPh + 16*464 + ks*32);
            ldmx4(pl[0], aPl + ks*32);
            ldmx4(pl[1], aPl + 16*464 + ks*32);
            ldmx4t(vh[0], aVh + ks*16*144);
            ldmx4t(vh[1], aVh + ks*16*144 + 32);
            ldmx4t(vl[0], aVl + ks*16*144);
            ldmx4t(vl[1], aVl + ks*16*144 + 32);
#pragma unroll
            for (int mi = 0; mi < 2; mi++)
#pragma unroll
                for (int nj = 0; nj < 4; nj++) {
                    const uint32_t* bhp = &vh[nj >> 1][(nj & 1) * 2];
                    const uint32_t* blp = &vl[nj >> 1][(nj & 1) * 2];
                    mma_bf16(c2[mi][nj], ph[mi], bhp);
                    mma_bf16(c2[mi][nj], pl[mi], bhp);
                    mma_bf16(c2[mi][nj], ph[mi], blp);
                }
        }
    }

#pragma unroll
    for (int mi = 0; mi < 2; mi++)
#pragma unroll
        for (int hf = 0; hf < 2; hf++) {
            int row = wm*32 + mi*16 + qr + hf*8;
            int qg  = q0g + row;
            if (qg >= Ss) continue;
            size_t base = ((size_t)(b*Ss + qg)*Ff + f)*Dd + h*64;
#pragma unroll
            for (int nj = 0; nj < 4; nj++) {
                int col = wn*32 + nj*8 + qc;
                uint32_t hb, lb;
                split2(c2[mi][nj][hf*2], c2[mi][nj][hf*2+1], hb, lb);
                *(uint32_t*)&XH[base + col] = hb;
                *(uint32_t*)&XL[base + col] = lb;
            }
        }
}

// ============================================================
// Diagonal gather on bf16 planes
// ============================================================
__global__ void diag_kernel(const uint2* __restrict__ XH, const uint2* __restrict__ XL,
                            uint2* __restrict__ XDH, uint2* __restrict__ XDL)
{
    int idx = blockIdx.x * blockDim.x + threadIdx.x;
    if (idx >= BSD/4) return;
    int c4   = idx % (Dd/4);
    int rest = idx / (Dd/4);
    int s = rest % Ss;
    int b = rest / Ss;
    int f = s / NSP;
    size_t src = ((size_t)(b*Ss + s)*Ff + f)*(Dd/4) + c4;
    XDH[idx] = XH[src];
    XDL[idx] = XL[src];
}

// ============================================================
// traj: per token — logits from x·m + q2·bk2, softmax over F,
// xw[h] = sum_f attn*x_f -> bf16 planes
// ============================================================
__global__ __launch_bounds__(128) void traj_kernel(
    const __nv_bfloat16* __restrict__ xh, const __nv_bfloat16* __restrict__ xl,
    const __nv_bfloat16* __restrict__ q2h, const __nv_bfloat16* __restrict__ q2l,
    const float* __restrict__ M_, const float* __restrict__ bpkv,
    __nv_bfloat16* __restrict__ xwh, __nv_bfloat16* __restrict__ xwl)
{
    __shared__ float xs[Ff][768];
    __shared__ float bq[Hh];
    const int t = blockIdx.x;
    const int tid = threadIdx.x;
    const int wid = tid >> 5, lane = tid & 31;

    {
        const uint4* ph = (const uint4*)(xh + (size_t)t*Ff*768);
        const uint4* pl = (const uint4*)(xl + (size_t)t*Ff*768);
        for (int i = tid; i < 768; i += 128) {
            uint4 vh = ph[i], vl = pl[i];
            int f = (i * 8) / 768, j = (i * 8) % 768;
            const uint32_t* wh = (const uint32_t*)&vh;
            const uint32_t* wl = (const uint32_t*)&vl;
#pragma unroll
            for (int w = 0; w < 4; w++) {
                float2 fh = __bfloat1622float2(*(const __nv_bfloat162*)&wh[w]);
                float2 fl = __bfloat1622float2(*(const __nv_bfloat162*)&wl[w]);
                xs[f][j + w*2 + 0] = fh.x + fl.x;
                xs[f][j + w*2 + 1] = fh.y + fl.y;
            }
        }
    }
#pragma unroll
    for (int hh = 0; hh < 3; hh++) {
        int h = wid * 3 + hh;
        int d0 = h*64 + lane;
        float qa = __bfloat162float(q2h[(size_t)t*768 + d0])      + __bfloat162float(q2l[(size_t)t*768 + d0]);
        float qb = __bfloat162float(q2h[(size_t)t*768 + d0 + 32]) + __bfloat162float(q2l[(size_t)t*768 + d0 + 32]);
        float acc = qa * bpkv[d0] + qb * bpkv[d0 + 32];
#pragma unroll
        for (int o = 16; o > 0; o >>= 1) acc += __shfl_xor_sync(0xffffffffu, acc, o);
        if (lane == 0) bq[h] = acc;
    }
    __syncthreads();

#pragma unroll
    for (int hh = 0; hh < 3; hh++) {
        int h = wid * 3 + hh;
        const float* mh = M_ + (size_t)t*(Hh*768) + (size_t)h*768;
        float acc[Ff];
#pragma unroll
        for (int f = 0; f < Ff; f++) acc[f] = 0.f;
        for (int js = 0; js < 24; js++) {
            int j = js*32 + lane;
            float mv = mh[j];
#pragma unroll
            for (int f = 0; f < Ff; f++) acc[f] += xs[f][j] * mv;
        }
        float lg[Ff];
#pragma unroll
        for (int f = 0; f < Ff; f++) {
            float s = acc[f];
#pragma unroll
            for (int o = 16; o > 0; o >>= 1) s += __shfl_xor_sync(0xffffffffu, s, o);
            lg[f] = SCALE * (s + bq[h]);
        }
        float mm = lg[0];
#pragma unroll
        for (int f = 1; f < Ff; f++) mm = fmaxf(mm, lg[f]);
        float attn[Ff], sum = 0.f;
#pragma unroll
        for (int f = 0; f < Ff; f++) { attn[f] = __expf(lg[f] - mm); sum += attn[f]; }
        float inv = 1.f / sum;
#pragma unroll
        for (int f = 0; f < Ff; f++) attn[f] *= inv;

        size_t base = (size_t)t*(Hh*768) + (size_t)h*768;
        for (int i = 0; i < 12; i++) {
            int j0 = i*64 + lane*2;
            float a0 = 0.f, a1 = 0.f;
#pragma unroll
            for (int f = 0; f < Ff; f++) {
                a0 += attn[f] * xs[f][j0];
                a1 += attn[f] * xs[f][j0 + 1];
            }
            uint32_t hb, lb;
            split2(a0, a1, hb, lb);
            *(uint32_t*)&xwh[base + j0] = hb;
            *(uint32_t*)&xwl[base + j0] = lb;
        }
    }
}

// ============================================================
// launch
// ============================================================
extern "C" void kernel_launch(void* const* d_in, const int* in_sizes, int n_in,
                              void* d_out, int out_size)
{
    const float* query = (const float*)d_in[0];
    const float* key_t = (const float*)d_in[1];
    const float* value = (const float*)d_in[2];
    const float* Wq   = (const float*)d_in[3];
    const float* bq   = (const float*)d_in[4];
    const float* Wk   = (const float*)d_in[5];
    const float* bk   = (const float*)d_in[6];
    const float* Wv   = (const float*)d_in[7];
    const float* bv   = (const float*)d_in[8];
    const float* Wpq  = (const float*)d_in[9];
    const float* bpq  = (const float*)d_in[10];
    const float* Wpkv = (const float*)d_in[11];
    const float* bpkv = (const float*)d_in[12];
    const float* Wp   = (const float*)d_in[13];
    const float* bp   = (const float*)d_in[14];

    float* out = (float*)d_out;            // (B, S, D)
    float* sa  = out + BSD;                // (B*H, S, F, n)

    float *mbuf, *zerob, *bqkv;
    __nv_bfloat16 *wth, *wtl, *wk2h, *wk2l;
    __nv_bfloat16 *inh, *inl, *qkvh, *qkvl;
    __nv_bfloat16 *xh, *xl, *xdh, *xdl, *q2h, *q2l, *xwh, *xwl, *t2h, *t2l;
    cudaGetSymbolAddress((void**)&mbuf, g_m);
    cudaGetSymbolAddress((void**)&zerob, g_zerob);
    cudaGetSymbolAddress((void**)&bqkv, g_bqkv);
    cudaGetSymbolAddress((void**)&wth, g_wth);
    cudaGetSymbolAddress((void**)&wtl, g_wtl);
    cudaGetSymbolAddress((void**)&wk2h, g_wk2h);
    cudaGetSymbolAddress((void**)&wk2l, g_wk2l);
    cudaGetSymbolAddress((void**)&inh, g_inh);
    cudaGetSymbolAddress((void**)&inl, g_inl);
    cudaGetSymbolAddress((void**)&qkvh, g_qkvh);
    cudaGetSymbolAddress((void**)&qkvl, g_qkvl);
    cudaGetSymbolAddress((void**)&xh,  g_xh);
    cudaGetSymbolAddress((void**)&xl,  g_xl);
    cudaGetSymbolAddress((void**)&xdh, g_xdh);
    cudaGetSymbolAddress((void**)&xdl, g_xdl);
    cudaGetSymbolAddress((void**)&q2h, g_q2h);
    cudaGetSymbolAddress((void**)&q2l, g_q2l);
    cudaGetSymbolAddress((void**)&xwh, g_xwh);
    cudaGetSymbolAddress((void**)&xwl, g_xwl);
    cudaGetSymbolAddress((void**)&t2h, g_t2h);
    cudaGetSymbolAddress((void**)&t2l, g_t2l);

    cudaFuncSetAttribute(stage1_mma_kernel,
                         cudaFuncAttributeMaxDynamicSharedMemorySize, S1_SMEM);
    cudaFuncSetAttribute(gemm_tpl<0,128>,
                         cudaFuncAttributeMaxDynamicSharedMemorySize, SMEM_128);
    cudaFuncSetAttribute(gemm_tpl<1,128>,
                         cudaFuncAttributeMaxDynamicSharedMemorySize, SMEM_128);
    cudaFuncSetAttribute(gemm_tpl<1,64>,
                         cudaFuncAttributeMaxDynamicSharedMemorySize, SMEM_64);
    cudaFuncSetAttribute(gemm_tpl<0,64>,
                         cudaFuncAttributeMaxDynamicSharedMemorySize, SMEM_64);

    int n4 = BSD/4, sg = (n4 + 255)/256;
    dim3 wb(32, 8);

    // launch 0: merged wtrans for Wq|Wk|Wv
    wtrans3_kernel<<<dim3(24,24,3), wb>>>(Wq, Wk, Wv, wth, wtl);
    // launch 1: merged input split
    split3_kernel<<<dim3(sg,3), 256>>>((const float4*)query, (const float4*)key_t,
                                       (const float4*)value, (uint2*)inh, (uint2*)inl, n4);
    // launch 2: bias pack
    biaspack_kernel<<<9, 256>>>(bq, bk, bv, bqkv);

    // launch 3 (ncu capture target): merged q/k/v projection, grid z=3
    gemm_tpl<1,128><<<dim3(6,25,3), 256, SMEM_128>>>(
        inh, inl, 768, (long)BSD,
        wth+OFF_WQ, wtl+OFF_WQ, 768, (long)WSQ,
        bqkv, 768,
        nullptr, qkvh, qkvl, 768, (long)BSD,
        BS, 768);

    // remaining weight prep
    wtrans_kernel<<<dim3(24,24), wb>>>(Wpq, wth+OFF_WPQ, wtl+OFF_WPQ, 768, 768);
    wtrans_kernel<<<dim3(24,24), wb>>>(Wp,  wth+OFF_WP,  wtl+OFF_WP,  768, 768);
    wtrans_kernel<<<dim3(48,24), wb>>>(Wpkv, wth+OFF_WPKV, wtl+OFF_WPKV, 768, 1536);
    splitwk2_kernel<<<(768*192 + 255)/256, 256>>>(Wpkv, wk2h, wk2l);

    stage1_mma_kernel<<<dim3(13, Ff, Bb*Hh), 256, S1_SMEM>>>(
        qkvh, qkvl, qkvh + BSD, qkvl + BSD, qkvh + 2*BSD, qkvl + 2*BSD, xh, xl, sa);

    diag_kernel<<<(BSD/4 + 255)/256, 256>>>(
        (const uint2*)xh, (const uint2*)xl, (uint2*)xdh, (uint2*)xdl);

    // q2 = xd @ Wpq + bpq  (split output), NTILE=64
    gemm_tpl<1,64><<<dim3(12, 25, 1), 256, SMEM_64>>>(
        xdh, xdl, 768, 0, wth+OFF_WPQ, wtl+OFF_WPQ, 768, 0,
        bpq, 0, nullptr, q2h, q2l, 768, 0, BS, 768);

    // m[t,h,:] = Wk2[:,hslice] @ q2_h : per-head GEMM M=BS, N=768, K=64
    gemm_tpl<0,128><<<dim3(6, 25, 12), 256, SMEM_128>>>(
        q2h, q2l, 768, 64,
        wk2h, wk2l, 768, 64,
        zerob, 0,
        mbuf, nullptr, nullptr, Hh*768, 768,
        BS, 64);

    // logits + softmax + xw
    traj_kernel<<<BS, 128>>>(xh, xl, q2h, q2l, mbuf, bpkv, xwh, xwl);

    // o_h = xw_h @ Wv2[:,hslice] + bv2_h : per-head GEMM M=BS, N=64, K=768 -> t2 planes
    gemm_tpl<1,64><<<dim3(1, 25, 12), 256, SMEM_64>>>(
        xwh, xwl, Hh*768, 768,
        wth + OFF_WPKV + (size_t)768*768, wtl + OFF_WPKV + (size_t)768*768, 768, (long)64*768,
        bpkv + 768, 64,
        nullptr, t2h, t2l, 768, 64,
        BS, 768);

    // out = t2 @ Wp + bp, NTILE=64
    gemm_tpl<0,64><<<dim3(12, 25, 1), 256, SMEM_64>>>(
        t2h, t2l, 768, 0, wth+OFF_WP, wtl+OFF_WP, 768, 0,
        bp, 0, out, nullptr, nullptr, 768, 0, BS, 768);
}